// round 1
// baseline (speedup 1.0000x reference)
#include <cuda_runtime.h>
#include <math.h>

#define SEQ    80
#define BATCH  256
#define EMBED  100
#define UNITS  2048

// ---------------- scratch (__device__ globals; no allocation allowed) -------
__device__ float g_x  [SEQ * BATCH * EMBED];   // gathered embeddings [20480,100]
__device__ float g_xw0[SEQ * BATCH * UNITS];   // precomputed x@W0+b0  (167 MB)
__device__ float g_h0 [2 * BATCH * UNITS];     // ping-pong h0
__device__ float g_h1 [2 * BATCH * UNITS];     // ping-pong h1

// ---------------- tiny utility kernels --------------------------------------
__global__ void zero2_kernel(float* a, float* b, int n) {
    int i = blockIdx.x * blockDim.x + threadIdx.x;
    if (i < n) { a[i] = 0.f; b[i] = 0.f; }
}

__global__ void gather_kernel(const int* __restrict__ inputs,
                              const float* __restrict__ emb,
                              float* __restrict__ X) {
    int row = blockIdx.x;                 // row = t*BATCH + b
    int t = row / BATCH, b = row % BATCH;
    int tok = inputs[b * SEQ + t];        // inputs is [BATCH, SEQ]
    for (int e = threadIdx.x; e < EMBED; e += blockDim.x)
        X[row * EMBED + e] = emb[tok * EMBED + e];
}

__global__ void final_kernel(const float* __restrict__ h1,
                             const float* __restrict__ Wo,
                             const float* __restrict__ bo,
                             float* __restrict__ out) {
    int b = blockIdx.x;
    float s = 0.f;
    for (int i = threadIdx.x; i < UNITS; i += blockDim.x)
        s += h1[b * UNITS + i] * Wo[i];
    for (int off = 16; off; off >>= 1) s += __shfl_down_sync(0xffffffffu, s, off);
    __shared__ float red[8];
    if ((threadIdx.x & 31) == 0) red[threadIdx.x >> 5] = s;
    __syncthreads();
    if (threadIdx.x == 0) {
        float t = 0.f;
        for (int w = 0; w < (int)(blockDim.x >> 5); w++) t += red[w];
        out[b] = 1.f / (1.f + expf(-(t + bo[0])));
    }
}

// ---------------- generic fused GEMM ----------------------------------------
// C[M,N] = act( A0[M,K0]@B0[K0,N] (+ A1[M,K1]@B1[K1,N]) (+ addend[M,N]) (+ bias[N]) )
// BM=BN=64, BK=16, 128 threads, per-thread 4x8. Requires M%64==0, N%64==0, K%4==0.
#define BM 64
#define BN 64
#define BK 16
#define TM 4
#define TN 8

__device__ __forceinline__ void load_tile(const float* __restrict__ A,
                                          const float* __restrict__ B,
                                          int K, int N, int cm, int cn, int k0,
                                          float (*As)[BM], float (*Bs)[BN], int tid)
{
    // A tile 64x16 -> smem transposed As[k][m]
    int a_row = tid >> 2;            // 0..31
    int a_k   = (tid & 3) << 2;      // 0,4,8,12
    #pragma unroll
    for (int h = 0; h < 2; h++) {
        int r = a_row + h * 32;
        float4 v = make_float4(0.f, 0.f, 0.f, 0.f);
        if (k0 + a_k < K)
            v = *(const float4*)(A + (size_t)(cm + r) * K + (k0 + a_k));
        As[a_k + 0][r] = v.x; As[a_k + 1][r] = v.y;
        As[a_k + 2][r] = v.z; As[a_k + 3][r] = v.w;
    }
    // B tile 16x64 -> smem row-major Bs[k][n]
    int b_row = tid >> 4;            // 0..7
    int b_col = (tid & 15) << 2;     // 0..60
    #pragma unroll
    for (int h = 0; h < 2; h++) {
        int r = b_row + h * 8;
        float4 v = make_float4(0.f, 0.f, 0.f, 0.f);
        if (k0 + r < K)
            v = *(const float4*)(B + (size_t)(k0 + r) * N + cn + b_col);
        *(float4*)&Bs[r][b_col] = v;
    }
}

__global__ void __launch_bounds__(128)
gemm_rnn_kernel(const float* __restrict__ A0, const float* __restrict__ B0, int K0,
                const float* __restrict__ A1, const float* __restrict__ B1, int K1,
                const float* __restrict__ addend,   // [M,N] or null
                const float* __restrict__ bias,     // [N] or null
                float* __restrict__ C, int M, int N, int act)
{
    __shared__ float As[2][BK][BM];
    __shared__ float Bs[2][BK][BN];

    int tid = threadIdx.x;
    int cm = blockIdx.y * BM;
    int cn = blockIdx.x * BN;
    int tr = tid >> 3;   // 0..15 -> rows tr*4..tr*4+3
    int tc = tid & 7;    // 0..7  -> cols tc*8..tc*8+7

    float acc[TM][TN];
    #pragma unroll
    for (int i = 0; i < TM; i++)
        #pragma unroll
        for (int j = 0; j < TN; j++) acc[i][j] = 0.f;

    #pragma unroll 1
    for (int p = 0; p < 2; p++) {
        const float* A = (p == 0) ? A0 : A1;
        const float* B = (p == 0) ? B0 : B1;
        int K         = (p == 0) ? K0 : K1;
        if (A == nullptr) continue;

        int nk = (K + BK - 1) / BK;
        int buf = 0;
        load_tile(A, B, K, N, cm, cn, 0, As[0], Bs[0], tid);
        __syncthreads();

        #pragma unroll 1
        for (int kt = 0; kt < nk; kt++) {
            if (kt + 1 < nk)
                load_tile(A, B, K, N, cm, cn, (kt + 1) * BK, As[buf ^ 1], Bs[buf ^ 1], tid);
            #pragma unroll
            for (int k = 0; k < BK; k++) {
                float4 av  = *(const float4*)&As[buf][k][tr * 4];
                float4 bv0 = *(const float4*)&Bs[buf][k][tc * 8];
                float4 bv1 = *(const float4*)&Bs[buf][k][tc * 8 + 4];
                float a[TM] = {av.x, av.y, av.z, av.w};
                float b[TN] = {bv0.x, bv0.y, bv0.z, bv0.w, bv1.x, bv1.y, bv1.z, bv1.w};
                #pragma unroll
                for (int i = 0; i < TM; i++)
                    #pragma unroll
                    for (int j = 0; j < TN; j++)
                        acc[i][j] = fmaf(a[i], b[j], acc[i][j]);
            }
            __syncthreads();
            buf ^= 1;
        }
        __syncthreads();
    }

    // epilogue
    #pragma unroll
    for (int i = 0; i < TM; i++) {
        int m = cm + tr * 4 + i;
        #pragma unroll
        for (int j = 0; j < TN; j += 4) {
            int n = cn + tc * 8 + j;
            float4 v = make_float4(acc[i][j], acc[i][j + 1], acc[i][j + 2], acc[i][j + 3]);
            if (addend) {
                float4 ad = *(const float4*)(addend + (size_t)m * N + n);
                v.x += ad.x; v.y += ad.y; v.z += ad.z; v.w += ad.w;
            }
            if (bias) {
                float4 bi = *(const float4*)(bias + n);
                v.x += bi.x; v.y += bi.y; v.z += bi.z; v.w += bi.w;
            }
            if (act) {
                v.x = tanhf(v.x); v.y = tanhf(v.y);
                v.z = tanhf(v.z); v.w = tanhf(v.w);
            }
            *(float4*)(C + (size_t)m * N + n) = v;
        }
    }
}

// ---------------- launch ------------------------------------------------------
extern "C" void kernel_launch(void* const* d_in, const int* in_sizes, int n_in,
                              void* d_out, int out_size)
{
    const int*   inputs = (const int*)  d_in[0];
    const float* emb    = (const float*)d_in[1];
    const float* W0     = (const float*)d_in[2];
    const float* U0     = (const float*)d_in[3];
    const float* b0     = (const float*)d_in[4];
    const float* W1     = (const float*)d_in[5];
    const float* U1     = (const float*)d_in[6];
    const float* b1     = (const float*)d_in[7];
    const float* Wo     = (const float*)d_in[8];
    const float* bo     = (const float*)d_in[9];
    float* out = (float*)d_out;

    float *x, *xw0, *h0, *h1;
    cudaGetSymbolAddress((void**)&x,   g_x);
    cudaGetSymbolAddress((void**)&xw0, g_xw0);
    cudaGetSymbolAddress((void**)&h0,  g_h0);
    cudaGetSymbolAddress((void**)&h1,  g_h1);

    float* h0c = h0;  float* h0n = h0 + (size_t)BATCH * UNITS;
    float* h1c = h1;  float* h1n = h1 + (size_t)BATCH * UNITS;

    const int HN = BATCH * UNITS;
    zero2_kernel<<<(HN + 255) / 256, 256>>>(h0c, h1c, HN);

    // hoisted: embedding gather + x@W0 + b0 for all timesteps
    gather_kernel<<<SEQ * BATCH, 128>>>(inputs, emb, x);
    gemm_rnn_kernel<<<dim3(UNITS / BN, (SEQ * BATCH) / BM), 128>>>(
        x, W0, EMBED, nullptr, nullptr, 0,
        nullptr, b0, xw0, SEQ * BATCH, UNITS, 0);

    dim3 grid(UNITS / BN, BATCH / BM);   // 32 x 4 = 128 CTAs
    for (int t = 0; t < SEQ; t++) {
        // h0' = tanh(xw0_t + h0 @ U0)
        gemm_rnn_kernel<<<grid, 128>>>(
            h0c, U0, UNITS, nullptr, nullptr, 0,
            xw0 + (size_t)t * BATCH * UNITS, nullptr, h0n, BATCH, UNITS, 1);
        // h1' = tanh(h0' @ W1 + h1 @ U1 + b1)
        gemm_rnn_kernel<<<grid, 128>>>(
            h0n, W1, UNITS, h1c, U1, UNITS,
            nullptr, b1, h1n, BATCH, UNITS, 1);
        float* tmp;
        tmp = h0c; h0c = h0n; h0n = tmp;
        tmp = h1c; h1c = h1n; h1n = tmp;
    }

    final_kernel<<<BATCH, 256>>>(h1c, Wo, bo, out);
}

// round 3
// speedup vs baseline: 1.9288x; 1.9288x over previous
#include <cuda_runtime.h>
#include <cuda_bf16.h>
#include <math.h>
#include <stdint.h>

#define SEQ    80
#define BATCH  256
#define EMBED  100
#define UNITS  2048
#define WK     4096          // weight row length: [hi(2048) | lo(2048)]
#define XK     256           // x row length: [hi(128 padded) | lo(128 padded)]
#define HROW   8192          // h row: [h0hi|h0lo|h1hi|h1lo] each 2048

// ---------------- scratch (__device__ globals; no allocation) ----------------
__device__ __nv_bfloat16 g_xe [SEQ * BATCH * XK];     // split embeddings
__device__ __nv_bfloat16 g_w0t[UNITS * XK];           // W0^T split  [n][256]
__device__ __nv_bfloat16 g_U0t[UNITS * WK];           // U0^T split  [n][4096]
__device__ __nv_bfloat16 g_W1t[UNITS * WK];
__device__ __nv_bfloat16 g_U1t[UNITS * WK];
__device__ float g_xw0[SEQ * BATCH * UNITS];          // x@W0+b0 (fp32)
__device__ __nv_bfloat16 g_hbuf[2][BATCH * HROW];     // ping-pong h state
__device__ float g_h1f[BATCH * UNITS];                // fp32 h1 for final dot

// ---------------- PTX helpers (sm_80-era only; no 'a' features) --------------
__device__ __forceinline__ uint32_t smem_u32(const void* p) {
    uint32_t a;
    asm("{ .reg .u64 t; cvta.to.shared.u64 t, %1; cvt.u32.u64 %0, t; }" : "=r"(a) : "l"(p));
    return a;
}
#define CP_ASYNC16(sp, gp) \
    asm volatile("cp.async.cg.shared.global [%0], [%1], 16;" :: "r"(sp), "l"(gp))
#define CP_COMMIT()  asm volatile("cp.async.commit_group;")
#define CP_WAIT1()   asm volatile("cp.async.wait_group 1;")
#define CP_WAIT0()   asm volatile("cp.async.wait_group 0;")

__device__ __forceinline__ void ldm_x4(uint32_t* r, uint32_t addr) {
    asm volatile("ldmatrix.sync.aligned.m8n8.x4.shared.b16 {%0,%1,%2,%3}, [%4];"
                 : "=r"(r[0]), "=r"(r[1]), "=r"(r[2]), "=r"(r[3]) : "r"(addr));
}
__device__ __forceinline__ void ldm_x2(uint32_t* r, uint32_t addr) {
    asm volatile("ldmatrix.sync.aligned.m8n8.x2.shared.b16 {%0,%1}, [%2];"
                 : "=r"(r[0]), "=r"(r[1]) : "r"(addr));
}
__device__ __forceinline__ void mma_bf16(float* d, const uint32_t* a, const uint32_t* b) {
    asm volatile("mma.sync.aligned.m16n8k16.row.col.f32.bf16.bf16.f32 "
                 "{%0,%1,%2,%3}, {%4,%5,%6,%7}, {%8,%9}, {%0,%1,%2,%3};"
                 : "+f"(d[0]), "+f"(d[1]), "+f"(d[2]), "+f"(d[3])
                 : "r"(a[0]), "r"(a[1]), "r"(a[2]), "r"(a[3]), "r"(b[0]), "r"(b[1]));
}

// ---------------- multi-pass fused GEMM (tensor core via mma.sync) -----------
// C[M,2048] = act( sum_p A_p[M,K_p] @ B_p^T  + addend + bias )
// B_p given as [2048][ldb] bf16, K-major rows (pre-transposed).
// Tile BM=BN=64, BK=32, 256 threads, 8 warps (2m x 4n), warp tile 32x16.
struct GemmArgs {
    const __nv_bfloat16* Ap[6];
    const __nv_bfloat16* Bp[6];
    int   nch[6];          // chunks of 32 per pass
    int   np;
    long  lda, ldb;
    const float* addend;   // [M,2048] or null
    const float* bias;     // [2048] or null
    __nv_bfloat16* outE;   // hi at col n, lo at col n+2048 (ldo); or null
    long  ldo;
    float* out32;          // [M,2048] or null
    int   act;
};

__device__ __forceinline__ int swz(int row, int c16) {
    return row * 64 + ((c16 ^ ((row >> 1) & 3)) << 4);
}

__device__ __forceinline__ void resolve_chunk(const GemmArgs& g, int cc,
                                              const __nv_bfloat16*& A,
                                              const __nv_bfloat16*& B, int& koff) {
    #pragma unroll
    for (int p = 0; p < 6; p++) {
        if (p < g.np) {
            if (cc < g.nch[p]) { A = g.Ap[p]; B = g.Bp[p]; koff = cc * 32; return; }
            cc -= g.nch[p];
        }
    }
    A = g.Ap[0]; B = g.Bp[0]; koff = 0;   // unreachable
}

__device__ __forceinline__ void load_chunk(const GemmArgs& g, int cc, int cm, int cn,
                                           char* a_s, char* b_s, int tid) {
    const __nv_bfloat16 *A, *B; int koff;
    resolve_chunk(g, cc, A, B, koff);
    int row = tid >> 2, c = tid & 3;
    const void* gA = A + (size_t)(cm + row) * g.lda + koff + c * 8;
    CP_ASYNC16(smem_u32(a_s + swz(row, c)), gA);
    const void* gB = B + (size_t)(cn + row) * g.ldb + koff + c * 8;
    CP_ASYNC16(smem_u32(b_s + swz(row, c)), gB);
}

__global__ void __launch_bounds__(256)
mma_gemm_kernel(GemmArgs g)
{
    __shared__ __align__(16) char sA[2][64 * 64];
    __shared__ __align__(16) char sB[2][64 * 64];

    int tid  = threadIdx.x;
    int lane = tid & 31;
    int wid  = tid >> 5;
    int wm   = wid >> 2;     // 0..1  -> 32 rows each
    int wn   = wid & 3;      // 0..3  -> 16 cols each
    int cm = blockIdx.y * 64;
    int cn = blockIdx.x * 64;

    float acc[2][2][4];
    #pragma unroll
    for (int i = 0; i < 2; i++)
        #pragma unroll
        for (int j = 0; j < 2; j++)
            #pragma unroll
            for (int k = 0; k < 4; k++) acc[i][j][k] = 0.f;

    int NC = 0;
    #pragma unroll
    for (int p = 0; p < 6; p++) if (p < g.np) NC += g.nch[p];

    load_chunk(g, 0, cm, cn, sA[0], sB[0], tid);
    CP_COMMIT();

    for (int c = 0; c < NC; c++) {
        int cur = c & 1;
        if (c + 1 < NC) {
            load_chunk(g, c + 1, cm, cn, sA[cur ^ 1], sB[cur ^ 1], tid);
            CP_COMMIT();
            CP_WAIT1();
        } else {
            CP_WAIT0();
        }
        __syncthreads();

        #pragma unroll
        for (int ks = 0; ks < 2; ks++) {
            uint32_t a[2][4], b[2][2];
            #pragma unroll
            for (int mi = 0; mi < 2; mi++) {
                int arow = wm * 32 + mi * 16 + (lane & 15);
                int ac   = ks * 2 + (lane >> 4);
                ldm_x4(a[mi], smem_u32(sA[cur] + swz(arow, ac)));
            }
            #pragma unroll
            for (int ni = 0; ni < 2; ni++) {
                int brow = wn * 16 + ni * 8 + (lane & 7);
                int bc   = ks * 2 + ((lane >> 3) & 1);
                ldm_x2(b[ni], smem_u32(sB[cur] + swz(brow, bc)));
            }
            #pragma unroll
            for (int mi = 0; mi < 2; mi++)
                #pragma unroll
                for (int ni = 0; ni < 2; ni++)
                    mma_bf16(acc[mi][ni], a[mi], b[ni]);
        }
        __syncthreads();
    }

    // epilogue
    int r_base = cm + wm * 32 + (lane >> 2);
    int c_base = cn + wn * 16 + (lane & 3) * 2;
    #pragma unroll
    for (int mi = 0; mi < 2; mi++) {
        #pragma unroll
        for (int ni = 0; ni < 2; ni++) {
            #pragma unroll
            for (int half = 0; half < 2; half++) {
                int row = r_base + mi * 16 + half * 8;
                int col = c_base + ni * 8;
                float v0 = acc[mi][ni][half * 2 + 0];
                float v1 = acc[mi][ni][half * 2 + 1];
                if (g.addend) {
                    float2 ad = *(const float2*)&g.addend[(size_t)row * UNITS + col];
                    v0 += ad.x; v1 += ad.y;
                }
                if (g.bias) {
                    float2 bi = *(const float2*)&g.bias[col];
                    v0 += bi.x; v1 += bi.y;
                }
                if (g.act) { v0 = tanhf(v0); v1 = tanhf(v1); }
                if (g.out32)
                    *(float2*)&g.out32[(size_t)row * UNITS + col] = make_float2(v0, v1);
                if (g.outE) {
                    __nv_bfloat16 h0 = __float2bfloat16(v0);
                    __nv_bfloat16 h1 = __float2bfloat16(v1);
                    __nv_bfloat16 l0 = __float2bfloat16(v0 - __bfloat162float(h0));
                    __nv_bfloat16 l1 = __float2bfloat16(v1 - __bfloat162float(h1));
                    __nv_bfloat162 hp; hp.x = h0; hp.y = h1;
                    __nv_bfloat162 lp; lp.x = l0; lp.y = l1;
                    *(__nv_bfloat162*)&g.outE[(size_t)row * g.ldo + col]         = hp;
                    *(__nv_bfloat162*)&g.outE[(size_t)row * g.ldo + UNITS + col] = lp;
                }
            }
        }
    }
}

// ---------------- weight prep kernels ----------------------------------------
// W [2048][2048] fp32 -> out [n][4096] bf16: [0..2048)=hi, [2048..4096)=lo
__global__ void wsplit_kernel(const float* __restrict__ W, __nv_bfloat16* __restrict__ out) {
    __shared__ float tile[32][33];
    int k0 = blockIdx.y * 32, n0 = blockIdx.x * 32;
    #pragma unroll
    for (int r = 0; r < 4; r++)
        tile[threadIdx.y + 8 * r][threadIdx.x] =
            W[(size_t)(k0 + threadIdx.y + 8 * r) * UNITS + n0 + threadIdx.x];
    __syncthreads();
    #pragma unroll
    for (int r = 0; r < 4; r++) {
        int n = n0 + threadIdx.y + 8 * r;
        int k = k0 + threadIdx.x;
        float w = tile[threadIdx.x][threadIdx.y + 8 * r];
        __nv_bfloat16 hi = __float2bfloat16(w);
        __nv_bfloat16 lo = __float2bfloat16(w - __bfloat162float(hi));
        out[(size_t)n * WK + k]         = hi;
        out[(size_t)n * WK + UNITS + k] = lo;
    }
}

// W0 [100][2048] fp32 -> out [n][256]: [0..128)=hi(pad0), [128..256)=lo
__global__ void w0split_kernel(const float* __restrict__ W0, __nv_bfloat16* __restrict__ out) {
    int n = blockIdx.x;
    int k = threadIdx.x;           // 0..127
    float v = (k < EMBED) ? W0[(size_t)k * UNITS + n] : 0.f;
    __nv_bfloat16 hi = __float2bfloat16(v);
    __nv_bfloat16 lo = __float2bfloat16(v - __bfloat162float(hi));
    out[(size_t)n * XK + k]       = hi;
    out[(size_t)n * XK + 128 + k] = lo;
}

// embedding gather + split: xe [t*BATCH+b][256]
__global__ void gather_split_kernel(const int* __restrict__ inputs,
                                    const float* __restrict__ emb,
                                    __nv_bfloat16* __restrict__ xe) {
    int row = blockIdx.x;
    int t = row / BATCH, b = row % BATCH;
    int tok = inputs[b * SEQ + t];
    int k = threadIdx.x;           // 0..127
    float v = (k < EMBED) ? emb[(size_t)tok * EMBED + k] : 0.f;
    __nv_bfloat16 hi = __float2bfloat16(v);
    __nv_bfloat16 lo = __float2bfloat16(v - __bfloat162float(hi));
    xe[(size_t)row * XK + k]       = hi;
    xe[(size_t)row * XK + 128 + k] = lo;
}

__global__ void zero_u32_kernel(uint32_t* p, int n) {
    int i = blockIdx.x * blockDim.x + threadIdx.x;
    if (i < n) p[i] = 0u;
}

__global__ void final_kernel(const float* __restrict__ h1,
                             const float* __restrict__ Wo,
                             const float* __restrict__ bo,
                             float* __restrict__ out) {
    int b = blockIdx.x;
    float s = 0.f;
    for (int i = threadIdx.x; i < UNITS; i += blockDim.x)
        s += h1[b * UNITS + i] * Wo[i];
    for (int off = 16; off; off >>= 1) s += __shfl_down_sync(0xffffffffu, s, off);
    __shared__ float red[8];
    if ((threadIdx.x & 31) == 0) red[threadIdx.x >> 5] = s;
    __syncthreads();
    if (threadIdx.x == 0) {
        float t = 0.f;
        for (int w = 0; w < (int)(blockDim.x >> 5); w++) t += red[w];
        out[b] = 1.f / (1.f + expf(-(t + bo[0])));
    }
}

// ---------------- launch ------------------------------------------------------
extern "C" void kernel_launch(void* const* d_in, const int* in_sizes, int n_in,
                              void* d_out, int out_size)
{
    const int*   inputs = (const int*)  d_in[0];
    const float* emb    = (const float*)d_in[1];
    const float* W0     = (const float*)d_in[2];
    const float* U0     = (const float*)d_in[3];
    const float* b0     = (const float*)d_in[4];
    const float* W1     = (const float*)d_in[5];
    const float* U1     = (const float*)d_in[6];
    const float* b1     = (const float*)d_in[7];
    const float* Wo     = (const float*)d_in[8];
    const float* bo     = (const float*)d_in[9];
    float* out = (float*)d_out;

    __nv_bfloat16 *xe, *w0t, *U0t, *W1t, *U1t, *hbuf;
    float *xw0, *h1f;
    cudaGetSymbolAddress((void**)&xe,   g_xe);
    cudaGetSymbolAddress((void**)&w0t,  g_w0t);
    cudaGetSymbolAddress((void**)&U0t,  g_U0t);
    cudaGetSymbolAddress((void**)&W1t,  g_W1t);
    cudaGetSymbolAddress((void**)&U1t,  g_U1t);
    cudaGetSymbolAddress((void**)&xw0,  g_xw0);
    cudaGetSymbolAddress((void**)&hbuf, g_hbuf);
    cudaGetSymbolAddress((void**)&h1f,  g_h1f);

    // weight prep
    dim3 wgrid(UNITS / 32, UNITS / 32), wblk(32, 8);
    wsplit_kernel<<<wgrid, wblk>>>(U0, U0t);
    wsplit_kernel<<<wgrid, wblk>>>(W1, W1t);
    wsplit_kernel<<<wgrid, wblk>>>(U1, U1t);
    w0split_kernel<<<UNITS, 128>>>(W0, w0t);

    // h state buffer 0 = zeros
    int zn = BATCH * HROW * 2 / 4;
    zero_u32_kernel<<<(zn + 255) / 256, 256>>>((uint32_t*)hbuf, zn);

    // embeddings + xw0 = x@W0 + b0 (3-pass split GEMM)
    gather_split_kernel<<<SEQ * BATCH, 128>>>(inputs, emb, xe);
    {
        GemmArgs g{};
        g.Ap[0] = xe;        g.Bp[0] = w0t;        g.nch[0] = 4;
        g.Ap[1] = xe + 128;  g.Bp[1] = w0t;        g.nch[1] = 4;
        g.Ap[2] = xe;        g.Bp[2] = w0t + 128;  g.nch[2] = 4;
        g.np = 3; g.lda = XK; g.ldb = XK;
        g.addend = nullptr; g.bias = b0;
        g.outE = nullptr; g.ldo = 0; g.out32 = xw0; g.act = 0;
        mma_gemm_kernel<<<dim3(UNITS / 64, (SEQ * BATCH) / 64), 256>>>(g);
    }

    __nv_bfloat16* cur = hbuf;
    __nv_bfloat16* nxt = hbuf + (size_t)BATCH * HROW;
    dim3 sgrid(UNITS / 64, BATCH / 64);   // 32 x 4 = 128 CTAs

    for (int t = 0; t < SEQ; t++) {
        // layer 1: h0' = tanh(xw0_t + h0 @ U0)
        {
            GemmArgs g{};
            g.Ap[0] = cur;         g.Bp[0] = U0t;         g.nch[0] = 64;
            g.Ap[1] = cur + 2048;  g.Bp[1] = U0t;         g.nch[1] = 64;
            g.Ap[2] = cur;         g.Bp[2] = U0t + 2048;  g.nch[2] = 64;
            g.np = 3; g.lda = HROW; g.ldb = WK;
            g.addend = xw0 + (size_t)t * BATCH * UNITS; g.bias = nullptr;
            g.outE = nxt; g.ldo = HROW; g.out32 = nullptr; g.act = 1;
            mma_gemm_kernel<<<sgrid, 256>>>(g);
        }
        // layer 2: h1' = tanh(h0' @ W1 + h1 @ U1 + b1)
        {
            GemmArgs g{};
            g.Ap[0] = nxt;         g.Bp[0] = W1t;         g.nch[0] = 64;
            g.Ap[1] = nxt + 2048;  g.Bp[1] = W1t;         g.nch[1] = 64;
            g.Ap[2] = nxt;         g.Bp[2] = W1t + 2048;  g.nch[2] = 64;
            g.Ap[3] = cur + 4096;  g.Bp[3] = U1t;         g.nch[3] = 64;
            g.Ap[4] = cur + 6144;  g.Bp[4] = U1t;         g.nch[4] = 64;
            g.Ap[5] = cur + 4096;  g.Bp[5] = U1t + 2048;  g.nch[5] = 64;
            g.np = 6; g.lda = HROW; g.ldb = WK;
            g.addend = nullptr; g.bias = b1;
            g.outE = nxt + 4096; g.ldo = HROW; g.out32 = h1f; g.act = 1;
            mma_gemm_kernel<<<sgrid, 256>>>(g);
        }
        __nv_bfloat16* tmp = cur; cur = nxt; nxt = tmp;
    }

    final_kernel<<<BATCH, 256>>>(h1f, Wo, bo, out);
}

// round 4
// speedup vs baseline: 4.3742x; 2.2678x over previous
#include <cuda_runtime.h>
#include <cuda_bf16.h>
#include <math.h>
#include <stdint.h>

#define SEQ    80
#define BATCH  256
#define EMBED  100
#define UNITS  2048
#define WK     4096          // weight row: [hi(2048) | lo(2048)]
#define XK     256           // x row: [hi(128 pad) | lo(128 pad)]
#define HROW   8192          // h row: [h0hi|h0lo|h1hi|h1lo]

// ---------------- scratch ----------------------------------------------------
__device__ __nv_bfloat16 g_xe [SEQ * BATCH * XK];
__device__ __nv_bfloat16 g_w0t[UNITS * XK];
__device__ __nv_bfloat16 g_U0t[UNITS * WK];
__device__ __nv_bfloat16 g_W1t[UNITS * WK];
__device__ __nv_bfloat16 g_U1t[UNITS * WK];
__device__ float g_xw0[SEQ * BATCH * UNITS];
__device__ __nv_bfloat16 g_hbuf[2][BATCH * HROW];
__device__ float g_h1f[BATCH * UNITS];

// ---------------- PTX helpers (portable, no sm_103a-gated features) ----------
__device__ __forceinline__ uint32_t smem_u32(const void* p) {
    uint32_t a;
    asm("{ .reg .u64 t; cvta.to.shared.u64 t, %1; cvt.u32.u64 %0, t; }" : "=r"(a) : "l"(p));
    return a;
}
#define CP_ASYNC16(sp, gp) \
    asm volatile("cp.async.cg.shared.global [%0], [%1], 16;" :: "r"(sp), "l"(gp))
#define CP_COMMIT()  asm volatile("cp.async.commit_group;")
#define CP_WAIT1()   asm volatile("cp.async.wait_group 1;")
#define CP_WAIT0()   asm volatile("cp.async.wait_group 0;")

__device__ __forceinline__ void ldm_x4(uint32_t* r, uint32_t addr) {
    asm volatile("ldmatrix.sync.aligned.m8n8.x4.shared.b16 {%0,%1,%2,%3}, [%4];"
                 : "=r"(r[0]), "=r"(r[1]), "=r"(r[2]), "=r"(r[3]) : "r"(addr));
}
__device__ __forceinline__ void ldm_x2(uint32_t* r, uint32_t addr) {
    asm volatile("ldmatrix.sync.aligned.m8n8.x2.shared.b16 {%0,%1}, [%2];"
                 : "=r"(r[0]), "=r"(r[1]) : "r"(addr));
}
__device__ __forceinline__ void mma_bf16(float* d, const uint32_t* a, const uint32_t* b) {
    asm volatile("mma.sync.aligned.m16n8k16.row.col.f32.bf16.bf16.f32 "
                 "{%0,%1,%2,%3}, {%4,%5,%6,%7}, {%8,%9}, {%0,%1,%2,%3};"
                 : "+f"(d[0]), "+f"(d[1]), "+f"(d[2]), "+f"(d[3])
                 : "r"(a[0]), "r"(a[1]), "r"(a[2]), "r"(a[3]), "r"(b[0]), "r"(b[1]));
}

// ---------------- fused split-GEMM ------------------------------------------
// C[M,2048] = act( sum_p (Ahi+Alo)@(Bhi+Blo)^T_p [3-term] + addend + bias )
// BM=BN=64, BK=64, 256 thr, 8 warps (2m x 4n). Tile row = 128B, SW128 swizzle.
#define TILE_BYTES 8192           // 64 rows x 128B
#define PROD_BYTES (4 * TILE_BYTES)

struct Prod { const __nv_bfloat16 *Ahi, *Alo, *Bhi, *Blo; };
struct Args {
    Prod pr[2];
    int  nprod, nchunk;           // nchunk = K/64 per product
    long lda, ldb;
    const float* addend;          // [M,2048] or null
    const float* bias;            // [2048] or null
    __nv_bfloat16* outE;          // hi @ col n, lo @ col n+2048; or null
    long ldo;
    float* out32;                 // [M,2048] or null
    int  act;
};

__device__ __forceinline__ int swz128(int row, int c16) {
    return row * 128 + ((c16 ^ (row & 7)) << 4);
}

__device__ __forceinline__ void load_tile(const __nv_bfloat16* src, long ld,
                                          int rbase, int kc, char* dst, int tid) {
    #pragma unroll
    for (int i = 0; i < 2; i++) {
        int slot = tid + i * 256;
        int row = slot >> 3, c16 = slot & 7;
        const void* g = src + (size_t)(rbase + row) * ld + kc * 64 + c16 * 8;
        CP_ASYNC16(smem_u32(dst + swz128(row, c16)), g);
    }
}

__device__ __forceinline__ void load_stage(const Args& a, int kc, char* st,
                                           int cm, int cn, int tid) {
    for (int p = 0; p < a.nprod; p++) {
        char* b = st + p * PROD_BYTES;
        load_tile(a.pr[p].Ahi, a.lda, cm, kc, b,                  tid);
        load_tile(a.pr[p].Alo, a.lda, cm, kc, b + TILE_BYTES,     tid);
        load_tile(a.pr[p].Bhi, a.ldb, cn, kc, b + 2 * TILE_BYTES, tid);
        load_tile(a.pr[p].Blo, a.ldb, cn, kc, b + 3 * TILE_BYTES, tid);
    }
}

__global__ void __launch_bounds__(256)
mma_gemm_kernel(Args g)
{
    extern __shared__ __align__(16) char sm[];
    int stage_bytes = g.nprod * PROD_BYTES;

    int tid  = threadIdx.x;
    int lane = tid & 31;
    int wid  = tid >> 5;
    int wm   = wid >> 2;      // 0..1
    int wn   = wid & 3;       // 0..3
    int cm = blockIdx.y * 64;
    int cn = blockIdx.x * 64;

    float acc[2][2][4];
    #pragma unroll
    for (int i = 0; i < 2; i++)
        #pragma unroll
        for (int j = 0; j < 2; j++)
            #pragma unroll
            for (int k = 0; k < 4; k++) acc[i][j][k] = 0.f;

    int NC = g.nchunk;
    load_stage(g, 0, sm, cm, cn, tid);
    CP_COMMIT();

    for (int c = 0; c < NC; c++) {
        char* cs = sm + (c & 1) * stage_bytes;
        if (c + 1 < NC) {
            load_stage(g, c + 1, sm + ((c + 1) & 1) * stage_bytes, cm, cn, tid);
            CP_COMMIT();
            CP_WAIT1();
        } else {
            CP_WAIT0();
        }
        __syncthreads();

        #pragma unroll
        for (int ks = 0; ks < 4; ks++) {
            for (int p = 0; p < g.nprod; p++) {
                char* pb = cs + p * PROD_BYTES;
                uint32_t ahi[2][4], alo[2][4], bhi[2][2], blo[2][2];
                #pragma unroll
                for (int mi = 0; mi < 2; mi++) {
                    int arow = wm * 32 + mi * 16 + (lane & 15);
                    int ac   = ks * 2 + (lane >> 4);
                    ldm_x4(ahi[mi], smem_u32(pb + swz128(arow, ac)));
                    ldm_x4(alo[mi], smem_u32(pb + TILE_BYTES + swz128(arow, ac)));
                }
                #pragma unroll
                for (int ni = 0; ni < 2; ni++) {
                    int brow = wn * 16 + ni * 8 + (lane & 7);
                    int bc   = ks * 2 + ((lane >> 3) & 1);
                    ldm_x2(bhi[ni], smem_u32(pb + 2 * TILE_BYTES + swz128(brow, bc)));
                    ldm_x2(blo[ni], smem_u32(pb + 3 * TILE_BYTES + swz128(brow, bc)));
                }
                #pragma unroll
                for (int mi = 0; mi < 2; mi++)
                    #pragma unroll
                    for (int ni = 0; ni < 2; ni++) {
                        mma_bf16(acc[mi][ni], ahi[mi], bhi[ni]);
                        mma_bf16(acc[mi][ni], alo[mi], bhi[ni]);
                        mma_bf16(acc[mi][ni], ahi[mi], blo[ni]);
                    }
            }
        }
        __syncthreads();
    }

    // epilogue
    int r_base = cm + wm * 32 + (lane >> 2);
    int c_base = cn + wn * 16 + (lane & 3) * 2;
    #pragma unroll
    for (int mi = 0; mi < 2; mi++) {
        #pragma unroll
        for (int ni = 0; ni < 2; ni++) {
            #pragma unroll
            for (int half = 0; half < 2; half++) {
                int row = r_base + mi * 16 + half * 8;
                int col = c_base + ni * 8;
                float v0 = acc[mi][ni][half * 2 + 0];
                float v1 = acc[mi][ni][half * 2 + 1];
                if (g.addend) {
                    float2 ad = *(const float2*)&g.addend[(size_t)row * UNITS + col];
                    v0 += ad.x; v1 += ad.y;
                }
                if (g.bias) {
                    float2 bi = *(const float2*)&g.bias[col];
                    v0 += bi.x; v1 += bi.y;
                }
                if (g.act) { v0 = tanhf(v0); v1 = tanhf(v1); }
                if (g.out32)
                    *(float2*)&g.out32[(size_t)row * UNITS + col] = make_float2(v0, v1);
                if (g.outE) {
                    __nv_bfloat16 h0 = __float2bfloat16(v0);
                    __nv_bfloat16 h1 = __float2bfloat16(v1);
                    __nv_bfloat16 l0 = __float2bfloat16(v0 - __bfloat162float(h0));
                    __nv_bfloat16 l1 = __float2bfloat16(v1 - __bfloat162float(h1));
                    __nv_bfloat162 hp; hp.x = h0; hp.y = h1;
                    __nv_bfloat162 lp; lp.x = l0; lp.y = l1;
                    *(__nv_bfloat162*)&g.outE[(size_t)row * g.ldo + col]         = hp;
                    *(__nv_bfloat162*)&g.outE[(size_t)row * g.ldo + UNITS + col] = lp;
                }
            }
        }
    }
}

// ---------------- prep kernels ------------------------------------------------
__global__ void wsplit_kernel(const float* __restrict__ W, __nv_bfloat16* __restrict__ out) {
    __shared__ float tile[32][33];
    int k0 = blockIdx.y * 32, n0 = blockIdx.x * 32;
    #pragma unroll
    for (int r = 0; r < 4; r++)
        tile[threadIdx.y + 8 * r][threadIdx.x] =
            W[(size_t)(k0 + threadIdx.y + 8 * r) * UNITS + n0 + threadIdx.x];
    __syncthreads();
    #pragma unroll
    for (int r = 0; r < 4; r++) {
        int n = n0 + threadIdx.y + 8 * r;
        int k = k0 + threadIdx.x;
        float w = tile[threadIdx.x][threadIdx.y + 8 * r];
        __nv_bfloat16 hi = __float2bfloat16(w);
        __nv_bfloat16 lo = __float2bfloat16(w - __bfloat162float(hi));
        out[(size_t)n * WK + k]         = hi;
        out[(size_t)n * WK + UNITS + k] = lo;
    }
}

__global__ void w0split_kernel(const float* __restrict__ W0, __nv_bfloat16* __restrict__ out) {
    int n = blockIdx.x;
    int k = threadIdx.x;
    float v = (k < EMBED) ? W0[(size_t)k * UNITS + n] : 0.f;
    __nv_bfloat16 hi = __float2bfloat16(v);
    __nv_bfloat16 lo = __float2bfloat16(v - __bfloat162float(hi));
    out[(size_t)n * XK + k]       = hi;
    out[(size_t)n * XK + 128 + k] = lo;
}

__global__ void gather_split_kernel(const int* __restrict__ inputs,
                                    const float* __restrict__ emb,
                                    __nv_bfloat16* __restrict__ xe) {
    int row = blockIdx.x;
    int t = row / BATCH, b = row % BATCH;
    int tok = inputs[b * SEQ + t];
    int k = threadIdx.x;
    float v = (k < EMBED) ? emb[(size_t)tok * EMBED + k] : 0.f;
    __nv_bfloat16 hi = __float2bfloat16(v);
    __nv_bfloat16 lo = __float2bfloat16(v - __bfloat162float(hi));
    xe[(size_t)row * XK + k]       = hi;
    xe[(size_t)row * XK + 128 + k] = lo;
}

__global__ void zero_u32_kernel(uint32_t* p, int n) {
    int i = blockIdx.x * blockDim.x + threadIdx.x;
    if (i < n) p[i] = 0u;
}

__global__ void final_kernel(const float* __restrict__ h1,
                             const float* __restrict__ Wo,
                             const float* __restrict__ bo,
                             float* __restrict__ out) {
    int b = blockIdx.x;
    float s = 0.f;
    for (int i = threadIdx.x; i < UNITS; i += blockDim.x)
        s += h1[b * UNITS + i] * Wo[i];
    for (int off = 16; off; off >>= 1) s += __shfl_down_sync(0xffffffffu, s, off);
    __shared__ float red[8];
    if ((threadIdx.x & 31) == 0) red[threadIdx.x >> 5] = s;
    __syncthreads();
    if (threadIdx.x == 0) {
        float t = 0.f;
        for (int w = 0; w < (int)(blockDim.x >> 5); w++) t += red[w];
        out[b] = 1.f / (1.f + expf(-(t + bo[0])));
    }
}

// ---------------- launch ------------------------------------------------------
extern "C" void kernel_launch(void* const* d_in, const int* in_sizes, int n_in,
                              void* d_out, int out_size)
{
    const int*   inputs = (const int*)  d_in[0];
    const float* emb    = (const float*)d_in[1];
    const float* W0     = (const float*)d_in[2];
    const float* U0     = (const float*)d_in[3];
    const float* b0     = (const float*)d_in[4];
    const float* W1     = (const float*)d_in[5];
    const float* U1     = (const float*)d_in[6];
    const float* b1     = (const float*)d_in[7];
    const float* Wo     = (const float*)d_in[8];
    const float* bo     = (const float*)d_in[9];
    float* out = (float*)d_out;

    __nv_bfloat16 *xe, *w0t, *U0t, *W1t, *U1t, *hbuf;
    float *xw0, *h1f;
    cudaGetSymbolAddress((void**)&xe,   g_xe);
    cudaGetSymbolAddress((void**)&w0t,  g_w0t);
    cudaGetSymbolAddress((void**)&U0t,  g_U0t);
    cudaGetSymbolAddress((void**)&W1t,  g_W1t);
    cudaGetSymbolAddress((void**)&U1t,  g_U1t);
    cudaGetSymbolAddress((void**)&xw0,  g_xw0);
    cudaGetSymbolAddress((void**)&hbuf, g_hbuf);
    cudaGetSymbolAddress((void**)&h1f,  g_h1f);

    static int smem_set = 0;
    if (!smem_set) {
        cudaFuncSetAttribute(mma_gemm_kernel,
                             cudaFuncAttributeMaxDynamicSharedMemorySize,
                             2 * 2 * PROD_BYTES);
        smem_set = 1;
    }

    // weight prep
    dim3 wgrid(UNITS / 32, UNITS / 32), wblk(32, 8);
    wsplit_kernel<<<wgrid, wblk>>>(U0, U0t);
    wsplit_kernel<<<wgrid, wblk>>>(W1, W1t);
    wsplit_kernel<<<wgrid, wblk>>>(U1, U1t);
    w0split_kernel<<<UNITS, 128>>>(W0, w0t);

    int zn = BATCH * HROW * 2 / 4;
    zero_u32_kernel<<<(zn + 255) / 256, 256>>>((uint32_t*)hbuf, zn);

    // xw0 = x @ W0 + b0
    gather_split_kernel<<<SEQ * BATCH, 128>>>(inputs, emb, xe);
    {
        Args g{};
        g.pr[0] = { xe, xe + 128, w0t, w0t + 128 };
        g.nprod = 1; g.nchunk = 2; g.lda = XK; g.ldb = XK;
        g.addend = nullptr; g.bias = b0;
        g.outE = nullptr; g.ldo = 0; g.out32 = xw0; g.act = 0;
        mma_gemm_kernel<<<dim3(UNITS / 64, (SEQ * BATCH) / 64), 256,
                          2 * PROD_BYTES>>>(g);
    }

    __nv_bfloat16* cur = hbuf;
    __nv_bfloat16* nxt = hbuf + (size_t)BATCH * HROW;
    dim3 sgrid(UNITS / 64, BATCH / 64);   // 128 CTAs

    for (int t = 0; t < SEQ; t++) {
        {   // layer 1: h0' = tanh(xw0_t + h0 @ U0)
            Args g{};
            g.pr[0] = { cur, cur + 2048, U0t, U0t + 2048 };
            g.nprod = 1; g.nchunk = UNITS / 64; g.lda = HROW; g.ldb = WK;
            g.addend = xw0 + (size_t)t * BATCH * UNITS; g.bias = nullptr;
            g.outE = nxt; g.ldo = HROW; g.out32 = nullptr; g.act = 1;
            mma_gemm_kernel<<<sgrid, 256, 2 * PROD_BYTES>>>(g);
        }
        {   // layer 2: h1' = tanh(h0' @ W1 + h1 @ U1 + b1)
            Args g{};
            g.pr[0] = { nxt,        nxt + 2048,  W1t, W1t + 2048 };
            g.pr[1] = { cur + 4096, cur + 6144,  U1t, U1t + 2048 };
            g.nprod = 2; g.nchunk = UNITS / 64; g.lda = HROW; g.ldb = WK;
            g.addend = nullptr; g.bias = b1;
            g.outE = nxt + 4096; g.ldo = HROW;
            g.out32 = (t == SEQ - 1) ? h1f : nullptr; g.act = 1;
            mma_gemm_kernel<<<sgrid, 256, 2 * 2 * PROD_BYTES>>>(g);
        }
        __nv_bfloat16* tmp = cur; cur = nxt; nxt = tmp;
    }

    final_kernel<<<BATCH, 256>>>(h1f, Wo, bo, out);
}

// round 6
// speedup vs baseline: 5.7722x; 1.3196x over previous
#include <cuda_runtime.h>
#include <cuda_bf16.h>
#include <math.h>
#include <stdint.h>

#define SEQ    80
#define BATCH  256
#define EMBED  100
#define UNITS  2048
#define WK     4096          // weight row: [hi(2048) | lo(2048)]
#define XK     256           // x row: [hi(128 pad) | lo(128 pad)]
#define HROW   8192          // h row: [h0hi|h0lo|h1hi|h1lo]

// ---------------- scratch ----------------------------------------------------
__device__ __nv_bfloat16 g_xe [SEQ * BATCH * XK];
__device__ __nv_bfloat16 g_w0t[UNITS * XK];
__device__ __nv_bfloat16 g_U0t[UNITS * WK];
__device__ __nv_bfloat16 g_W1t[UNITS * WK];
__device__ __nv_bfloat16 g_U1t[UNITS * WK];
__device__ float g_xw0[SEQ * BATCH * UNITS];
__device__ float g_p  [BATCH * UNITS];             // p = h1 @ U1 (fp32)
__device__ __nv_bfloat16 g_hbuf[2][BATCH * HROW];
__device__ float g_h1f[BATCH * UNITS];

// ---------------- PTX helpers -------------------------------------------------
__device__ __forceinline__ uint32_t smem_u32(const void* p) {
    uint32_t a;
    asm("{ .reg .u64 t; cvta.to.shared.u64 t, %1; cvt.u32.u64 %0, t; }" : "=r"(a) : "l"(p));
    return a;
}
#define CP_ASYNC16(sp, gp) \
    asm volatile("cp.async.cg.shared.global [%0], [%1], 16;" :: "r"(sp), "l"(gp))
#define CP_COMMIT()  asm volatile("cp.async.commit_group;")
#define CP_WAIT1()   asm volatile("cp.async.wait_group 1;")
#define CP_WAIT0()   asm volatile("cp.async.wait_group 0;")

__device__ __forceinline__ void ldm_x4(uint32_t* r, uint32_t addr) {
    asm volatile("ldmatrix.sync.aligned.m8n8.x4.shared.b16 {%0,%1,%2,%3}, [%4];"
                 : "=r"(r[0]), "=r"(r[1]), "=r"(r[2]), "=r"(r[3]) : "r"(addr));
}
__device__ __forceinline__ void mma_bf16(float* d, const uint32_t* a, const uint32_t* b) {
    asm volatile("mma.sync.aligned.m16n8k16.row.col.f32.bf16.bf16.f32 "
                 "{%0,%1,%2,%3}, {%4,%5,%6,%7}, {%8,%9}, {%0,%1,%2,%3};"
                 : "+f"(d[0]), "+f"(d[1]), "+f"(d[2]), "+f"(d[3])
                 : "r"(a[0]), "r"(a[1]), "r"(a[2]), "r"(a[3]), "r"(b[0]), "r"(b[1]));
}

__device__ __forceinline__ int swz128(int row, int c16) {
    return row * 128 + ((c16 ^ (row & 7)) << 4);
}

// ---------------- split-GEMM (one product, 3-term hi/lo) ----------------------
// C[M,2048-slice] = act( (Ahi+Alo)@(Bhi+Blo)^T + addend + bias ), B rows K-major.
struct Args {
    const __nv_bfloat16 *Ahi, *Alo, *Bhi, *Blo;
    int  nchunk;                  // K / 64
    long lda, ldb;
    const float* addend;          // [M,2048] or null
    const float* bias;            // [2048] or null
    __nv_bfloat16* outE;          // hi @ col n, lo @ col n+2048; or null
    long ldo;
    float* out32;                 // [M,2048] or null
    int  act;
};

template<int NROWS>
__device__ __forceinline__ void load_rows(const __nv_bfloat16* src, long ld,
                                          int rbase, int kc, char* dst, int tid) {
    #pragma unroll
    for (int i = 0; i < NROWS * 8 / 256; i++) {
        int s = tid + i * 256;
        int row = s >> 3, c16 = s & 7;
        const void* g = src + (size_t)(rbase + row) * ld + kc * 64 + c16 * 8;
        CP_ASYNC16(smem_u32(dst + swz128(row, c16)), g);
    }
}

// BM=64, BK=64, BN template (64 or 128). 256 threads, 8 warps (2m x 4n).
// Each warp: 32 rows x (BN/4) cols. One ldmatrix.x4 B-load covers a 16-col
// n-block (n16 x k16), so NI = BN/64 x4-loads per ks per type.
template<int BN>
__global__ void __launch_bounds__(256)
step_gemm(Args g0, Args g1)
{
    const Args g = (blockIdx.z == 0) ? g0 : g1;
    constexpr int NI = BN / 64;            // x4 B-loads per type per ks
    constexpr int TILE_A = 64 * 128;
    constexpr int TILE_B = BN * 128;
    constexpr int STAGE  = 2 * TILE_A + 2 * TILE_B;
    extern __shared__ __align__(16) char sm[];

    int tid  = threadIdx.x;
    int lane = tid & 31;
    int wid  = tid >> 5;
    int wm   = wid >> 2;                   // 0..1 -> 32 rows
    int wn   = wid & 3;                    // 0..3 -> BN/4 cols
    int cm = blockIdx.y * 64;
    int cn = blockIdx.x * BN;

    float acc[2][2 * NI][4];
    #pragma unroll
    for (int i = 0; i < 2; i++)
        #pragma unroll
        for (int j = 0; j < 2 * NI; j++)
            #pragma unroll
            for (int k = 0; k < 4; k++) acc[i][j][k] = 0.f;

    int NC = g.nchunk;

    auto issue = [&](int c) {
        char* st = sm + (c % 3) * STAGE;
        load_rows<64>(g.Ahi, g.lda, cm, c, st,              tid);
        load_rows<64>(g.Alo, g.lda, cm, c, st + TILE_A,     tid);
        load_rows<BN>(g.Bhi, g.ldb, cn, c, st + 2 * TILE_A, tid);
        load_rows<BN>(g.Blo, g.ldb, cn, c, st + 2 * TILE_A + TILE_B, tid);
        CP_COMMIT();
    };

    issue(0);
    if (NC > 1) issue(1);

    for (int c = 0; c < NC; c++) {
        if (c + 1 < NC) { CP_WAIT1(); } else { CP_WAIT0(); }
        __syncthreads();
        if (c + 2 < NC) issue(c + 2);

        char* cs = sm + (c % 3) * STAGE;
        char* pa_hi = cs;
        char* pa_lo = cs + TILE_A;
        char* pb_hi = cs + 2 * TILE_A;
        char* pb_lo = cs + 2 * TILE_A + TILE_B;

        #pragma unroll
        for (int ks = 0; ks < 4; ks++) {
            uint32_t ahi[2][4], alo[2][4], bhi[NI][4], blo[NI][4];
            #pragma unroll
            for (int mi = 0; mi < 2; mi++) {
                int arow = wm * 32 + mi * 16 + (lane & 15);
                int ac   = ks * 2 + (lane >> 4);
                ldm_x4(ahi[mi], smem_u32(pa_hi + swz128(arow, ac)));
                ldm_x4(alo[mi], smem_u32(pa_lo + swz128(arow, ac)));
            }
            #pragma unroll
            for (int np = 0; np < NI; np++) {
                int brow = wn * (BN / 4) + np * 16 + ((lane & 16) ? 8 : 0) + (lane & 7);
                int bc   = ks * 2 + ((lane >> 3) & 1);
                ldm_x4(bhi[np], smem_u32(pb_hi + swz128(brow, bc)));
                ldm_x4(blo[np], smem_u32(pb_lo + swz128(brow, bc)));
            }
            #pragma unroll
            for (int mi = 0; mi < 2; mi++)
                #pragma unroll
                for (int np = 0; np < NI; np++)
                    #pragma unroll
                    for (int h = 0; h < 2; h++) {
                        float* a_ = acc[mi][np * 2 + h];
                        mma_bf16(a_, ahi[mi], &bhi[np][h * 2]);
                        mma_bf16(a_, alo[mi], &bhi[np][h * 2]);
                        mma_bf16(a_, ahi[mi], &blo[np][h * 2]);
                    }
        }
        // buffer (c%3) is reused at c+3; the sync at iteration c+1 (before
        // issue(c+3)) guarantees all warps finished reading it.
    }

    // epilogue
    int r0 = cm + wm * 32 + (lane >> 2);
    int c0 = cn + wn * (BN / 4) + (lane & 3) * 2;
    #pragma unroll
    for (int mi = 0; mi < 2; mi++) {
        #pragma unroll
        for (int ni = 0; ni < 2 * NI; ni++) {
            #pragma unroll
            for (int h8 = 0; h8 < 2; h8++) {
                int row = r0 + mi * 16 + h8 * 8;
                int col = c0 + ni * 8;
                float v0 = acc[mi][ni][h8 * 2 + 0];
                float v1 = acc[mi][ni][h8 * 2 + 1];
                if (g.addend) {
                    float2 ad = *(const float2*)&g.addend[(size_t)row * UNITS + col];
                    v0 += ad.x; v1 += ad.y;
                }
                if (g.bias) {
                    float2 bi = *(const float2*)&g.bias[col];
                    v0 += bi.x; v1 += bi.y;
                }
                if (g.act) { v0 = tanhf(v0); v1 = tanhf(v1); }
                if (g.out32)
                    *(float2*)&g.out32[(size_t)row * UNITS + col] = make_float2(v0, v1);
                if (g.outE) {
                    __nv_bfloat16 h0 = __float2bfloat16(v0);
                    __nv_bfloat16 h1 = __float2bfloat16(v1);
                    __nv_bfloat16 l0 = __float2bfloat16(v0 - __bfloat162float(h0));
                    __nv_bfloat16 l1 = __float2bfloat16(v1 - __bfloat162float(h1));
                    __nv_bfloat162 hp; hp.x = h0; hp.y = h1;
                    __nv_bfloat162 lp; lp.x = l0; lp.y = l1;
                    *(__nv_bfloat162*)&g.outE[(size_t)row * g.ldo + col]         = hp;
                    *(__nv_bfloat162*)&g.outE[(size_t)row * g.ldo + UNITS + col] = lp;
                }
            }
        }
    }
}

// ---------------- prep kernels ------------------------------------------------
__global__ void wsplit_kernel(const float* __restrict__ W, __nv_bfloat16* __restrict__ out) {
    __shared__ float tile[32][33];
    int k0 = blockIdx.y * 32, n0 = blockIdx.x * 32;
    #pragma unroll
    for (int r = 0; r < 4; r++)
        tile[threadIdx.y + 8 * r][threadIdx.x] =
            W[(size_t)(k0 + threadIdx.y + 8 * r) * UNITS + n0 + threadIdx.x];
    __syncthreads();
    #pragma unroll
    for (int r = 0; r < 4; r++) {
        int n = n0 + threadIdx.y + 8 * r;
        int k = k0 + threadIdx.x;
        float w = tile[threadIdx.x][threadIdx.y + 8 * r];
        __nv_bfloat16 hi = __float2bfloat16(w);
        __nv_bfloat16 lo = __float2bfloat16(w - __bfloat162float(hi));
        out[(size_t)n * WK + k]         = hi;
        out[(size_t)n * WK + UNITS + k] = lo;
    }
}

__global__ void w0split_kernel(const float* __restrict__ W0, __nv_bfloat16* __restrict__ out) {
    int n = blockIdx.x;
    int k = threadIdx.x;
    float v = (k < EMBED) ? W0[(size_t)k * UNITS + n] : 0.f;
    __nv_bfloat16 hi = __float2bfloat16(v);
    __nv_bfloat16 lo = __float2bfloat16(v - __bfloat162float(hi));
    out[(size_t)n * XK + k]       = hi;
    out[(size_t)n * XK + 128 + k] = lo;
}

__global__ void gather_split_kernel(const int* __restrict__ inputs,
                                    const float* __restrict__ emb,
                                    __nv_bfloat16* __restrict__ xe) {
    int row = blockIdx.x;
    int t = row / BATCH, b = row % BATCH;
    int tok = inputs[b * SEQ + t];
    int k = threadIdx.x;
    float v = (k < EMBED) ? emb[(size_t)tok * EMBED + k] : 0.f;
    __nv_bfloat16 hi = __float2bfloat16(v);
    __nv_bfloat16 lo = __float2bfloat16(v - __bfloat162float(hi));
    xe[(size_t)row * XK + k]       = hi;
    xe[(size_t)row * XK + 128 + k] = lo;
}

__global__ void zero_u32_kernel(uint32_t* p, int n) {
    int i = blockIdx.x * blockDim.x + threadIdx.x;
    if (i < n) p[i] = 0u;
}

__global__ void final_kernel(const float* __restrict__ h1,
                             const float* __restrict__ Wo,
                             const float* __restrict__ bo,
                             float* __restrict__ out) {
    int b = blockIdx.x;
    float s = 0.f;
    for (int i = threadIdx.x; i < UNITS; i += blockDim.x)
        s += h1[b * UNITS + i] * Wo[i];
    for (int off = 16; off; off >>= 1) s += __shfl_down_sync(0xffffffffu, s, off);
    __shared__ float red[8];
    if ((threadIdx.x & 31) == 0) red[threadIdx.x >> 5] = s;
    __syncthreads();
    if (threadIdx.x == 0) {
        float t = 0.f;
        for (int w = 0; w < (int)(blockDim.x >> 5); w++) t += red[w];
        out[b] = 1.f / (1.f + expf(-(t + bo[0])));
    }
}

// ---------------- launch ------------------------------------------------------
extern "C" void kernel_launch(void* const* d_in, const int* in_sizes, int n_in,
                              void* d_out, int out_size)
{
    const int*   inputs = (const int*)  d_in[0];
    const float* emb    = (const float*)d_in[1];
    const float* W0     = (const float*)d_in[2];
    const float* U0     = (const float*)d_in[3];
    const float* b0     = (const float*)d_in[4];
    const float* W1     = (const float*)d_in[5];
    const float* U1     = (const float*)d_in[6];
    const float* b1     = (const float*)d_in[7];
    const float* Wo     = (const float*)d_in[8];
    const float* bo     = (const float*)d_in[9];
    float* out = (float*)d_out;

    __nv_bfloat16 *xe, *w0t, *U0t, *W1t, *U1t, *hbuf;
    float *xw0, *pbuf, *h1f;
    cudaGetSymbolAddress((void**)&xe,   g_xe);
    cudaGetSymbolAddress((void**)&w0t,  g_w0t);
    cudaGetSymbolAddress((void**)&U0t,  g_U0t);
    cudaGetSymbolAddress((void**)&W1t,  g_W1t);
    cudaGetSymbolAddress((void**)&U1t,  g_U1t);
    cudaGetSymbolAddress((void**)&xw0,  g_xw0);
    cudaGetSymbolAddress((void**)&pbuf, g_p);
    cudaGetSymbolAddress((void**)&hbuf, g_hbuf);
    cudaGetSymbolAddress((void**)&h1f,  g_h1f);

    const int SMEM128 = 3 * (2 * 64 * 128 + 2 * 128 * 128);   // 147456
    const int SMEM64  = 3 * (2 * 64 * 128 + 2 * 64 * 128);    // 98304
    static int smem_set = 0;
    if (!smem_set) {
        cudaFuncSetAttribute(step_gemm<128>,
                             cudaFuncAttributeMaxDynamicSharedMemorySize, SMEM128);
        cudaFuncSetAttribute(step_gemm<64>,
                             cudaFuncAttributeMaxDynamicSharedMemorySize, SMEM64);
        smem_set = 1;
    }

    // weight prep
    dim3 wgrid(UNITS / 32, UNITS / 32), wblk(32, 8);
    wsplit_kernel<<<wgrid, wblk>>>(U0, U0t);
    wsplit_kernel<<<wgrid, wblk>>>(W1, W1t);
    wsplit_kernel<<<wgrid, wblk>>>(U1, U1t);
    w0split_kernel<<<UNITS, 128>>>(W0, w0t);

    int zn = BATCH * HROW * 2 / 4;
    zero_u32_kernel<<<(zn + 255) / 256, 256>>>((uint32_t*)hbuf, zn);

    // xw0 = x @ W0 + b0
    gather_split_kernel<<<SEQ * BATCH, 128>>>(inputs, emb, xe);
    {
        Args g{};
        g.Ahi = xe; g.Alo = xe + 128; g.Bhi = w0t; g.Blo = w0t + 128;
        g.nchunk = 2; g.lda = XK; g.ldb = XK;
        g.addend = nullptr; g.bias = b0;
        g.outE = nullptr; g.ldo = 0; g.out32 = xw0; g.act = 0;
        step_gemm<128><<<dim3(UNITS / 128, (SEQ * BATCH) / 64, 1), 256, SMEM128>>>(g, g);
    }

    __nv_bfloat16* cur = hbuf;
    __nv_bfloat16* nxt = hbuf + (size_t)BATCH * HROW;

    for (int t = 0; t < SEQ; t++) {
        // combined: z=0 -> h0' = tanh(xw0_t + h0@U0); z=1 -> p = h1@U1
        {
            Args gl1{}, gp{};
            gl1.Ahi = cur;  gl1.Alo = cur + 2048;
            gl1.Bhi = U0t;  gl1.Blo = U0t + 2048;
            gl1.nchunk = UNITS / 64; gl1.lda = HROW; gl1.ldb = WK;
            gl1.addend = xw0 + (size_t)t * BATCH * UNITS; gl1.bias = nullptr;
            gl1.outE = nxt; gl1.ldo = HROW; gl1.out32 = nullptr; gl1.act = 1;

            gp.Ahi = cur + 4096; gp.Alo = cur + 6144;
            gp.Bhi = U1t;        gp.Blo = U1t + 2048;
            gp.nchunk = UNITS / 64; gp.lda = HROW; gp.ldb = WK;
            gp.addend = nullptr; gp.bias = nullptr;
            gp.outE = nullptr; gp.ldo = 0; gp.out32 = pbuf; gp.act = 0;

            step_gemm<128><<<dim3(UNITS / 128, BATCH / 64, 2), 256, SMEM128>>>(gl1, gp);
        }
        // L2b: h1' = tanh(h0'@W1 + p + b1)
        {
            Args g{};
            g.Ahi = nxt; g.Alo = nxt + 2048;
            g.Bhi = W1t; g.Blo = W1t + 2048;
            g.nchunk = UNITS / 64; g.lda = HROW; g.ldb = WK;
            g.addend = pbuf; g.bias = b1;
            g.outE = nxt + 4096; g.ldo = HROW;
            g.out32 = (t == SEQ - 1) ? h1f : nullptr; g.act = 1;
            step_gemm<64><<<dim3(UNITS / 64, BATCH / 64, 1), 256, SMEM64>>>(g, g);
        }
        __nv_bfloat16* tmp = cur; cur = nxt; nxt = tmp;
    }

    final_kernel<<<BATCH, 256>>>(h1f, Wo, bo, out);
}

// round 7
// speedup vs baseline: 6.0971x; 1.0563x over previous
#include <cuda_runtime.h>
#include <cuda_bf16.h>
#include <math.h>
#include <stdint.h>

#define SEQ    80
#define BATCH  256
#define EMBED  100
#define UNITS  2048
#define WK     4096          // weight row: [hi(2048) | lo(2048)]
#define XK     256           // x row: [hi(128 pad) | lo(128 pad)]
#define HROW   8192          // h row: [h0hi|h0lo|h1hi|h1lo]
#define NCTA   128

// ---------------- scratch ----------------------------------------------------
__device__ __nv_bfloat16 g_xe [SEQ * BATCH * XK];
__device__ __nv_bfloat16 g_w0t[UNITS * XK];
__device__ __nv_bfloat16 g_U0t[UNITS * WK];
__device__ __nv_bfloat16 g_W1t[UNITS * WK];
__device__ __nv_bfloat16 g_U1t[UNITS * WK];
__device__ float g_xw0[SEQ * BATCH * UNITS];
__device__ float g_p  [BATCH * UNITS];             // p = h1 @ U1 (fp32)
__device__ __nv_bfloat16 g_hbuf[2][BATCH * HROW];
__device__ float g_h1f[BATCH * UNITS];
__device__ unsigned g_bar[2 * SEQ + 8];            // grid-barrier counters

// ---------------- PTX helpers -------------------------------------------------
__device__ __forceinline__ uint32_t smem_u32(const void* p) {
    uint32_t a;
    asm("{ .reg .u64 t; cvta.to.shared.u64 t, %1; cvt.u32.u64 %0, t; }" : "=r"(a) : "l"(p));
    return a;
}
#define CP_ASYNC16(sp, gp) \
    asm volatile("cp.async.cg.shared.global [%0], [%1], 16;" :: "r"(sp), "l"(gp))
#define CP_COMMIT()  asm volatile("cp.async.commit_group;")
#define CP_WAIT1()   asm volatile("cp.async.wait_group 1;")
#define CP_WAIT0()   asm volatile("cp.async.wait_group 0;")

__device__ __forceinline__ void ldm_x4(uint32_t* r, uint32_t addr) {
    asm volatile("ldmatrix.sync.aligned.m8n8.x4.shared.b16 {%0,%1,%2,%3}, [%4];"
                 : "=r"(r[0]), "=r"(r[1]), "=r"(r[2]), "=r"(r[3]) : "r"(addr));
}
__device__ __forceinline__ void mma_bf16(float* d, const uint32_t* a, const uint32_t* b) {
    asm volatile("mma.sync.aligned.m16n8k16.row.col.f32.bf16.bf16.f32 "
                 "{%0,%1,%2,%3}, {%4,%5,%6,%7}, {%8,%9}, {%0,%1,%2,%3};"
                 : "+f"(d[0]), "+f"(d[1]), "+f"(d[2]), "+f"(d[3])
                 : "r"(a[0]), "r"(a[1]), "r"(a[2]), "r"(a[3]), "r"(b[0]), "r"(b[1]));
}

__device__ __forceinline__ int swz128(int row, int c16) {
    return row * 128 + ((c16 ^ (row & 7)) << 4);
}

// grid-wide barrier: one counter slot per use, all NCTA CTAs must arrive.
__device__ __forceinline__ void grid_sync(unsigned* bar, int s) {
    __syncthreads();
    if (threadIdx.x == 0) {
        __threadfence();
        atomicAdd(&bar[s], 1u);
        while (*((volatile unsigned*)&bar[s]) < NCTA) __nanosleep(64);
    }
    __syncthreads();
}

// ---------------- split-GEMM tile (3-term hi/lo) ------------------------------
struct Args {
    const __nv_bfloat16 *Ahi, *Alo, *Bhi, *Blo;
    int  nchunk;                  // K / 64
    long lda, ldb;
    const float* addend;          // [M,2048] or null (read via __ldcg)
    const float* bias;            // [2048] or null
    __nv_bfloat16* outE;          // hi @ col n, lo @ col n+2048; or null
    long ldo;
    float* out32;                 // [M,2048] or null
    int  act;
};

template<int NROWS>
__device__ __forceinline__ void load_rows(const __nv_bfloat16* src, long ld,
                                          int rbase, int kc, char* dst, int tid) {
    #pragma unroll
    for (int i = 0; i < NROWS * 8 / 256; i++) {
        int s = tid + i * 256;
        int row = s >> 3, c16 = s & 7;
        const void* g = src + (size_t)(rbase + row) * ld + kc * 64 + c16 * 8;
        CP_ASYNC16(smem_u32(dst + swz128(row, c16)), g);
    }
}

// BM=64, BK=64. 256 threads, 8 warps (2m x 4n); warp tile 32 x (BN/4).
template<int BN>
__device__ void gemm_tile(const Args& g, int cm, int cn, char* sm)
{
    constexpr int NI = BN / 64;
    constexpr int TILE_A = 64 * 128;
    constexpr int TILE_B = BN * 128;
    constexpr int STAGE  = 2 * TILE_A + 2 * TILE_B;

    int tid  = threadIdx.x;
    int lane = tid & 31;
    int wid  = tid >> 5;
    int wm   = wid >> 2;
    int wn   = wid & 3;

    float acc[2][2 * NI][4];
    #pragma unroll
    for (int i = 0; i < 2; i++)
        #pragma unroll
        for (int j = 0; j < 2 * NI; j++)
            #pragma unroll
            for (int k = 0; k < 4; k++) acc[i][j][k] = 0.f;

    int NC = g.nchunk;

    auto issue = [&](int c) {
        char* st = sm + (c % 3) * STAGE;
        load_rows<64>(g.Ahi, g.lda, cm, c, st,              tid);
        load_rows<64>(g.Alo, g.lda, cm, c, st + TILE_A,     tid);
        load_rows<BN>(g.Bhi, g.ldb, cn, c, st + 2 * TILE_A, tid);
        load_rows<BN>(g.Blo, g.ldb, cn, c, st + 2 * TILE_A + TILE_B, tid);
        CP_COMMIT();
    };

    issue(0);
    if (NC > 1) issue(1);

    for (int c = 0; c < NC; c++) {
        if (c + 1 < NC) { CP_WAIT1(); } else { CP_WAIT0(); }
        __syncthreads();
        if (c + 2 < NC) issue(c + 2);

        char* cs = sm + (c % 3) * STAGE;
        char* pa_hi = cs;
        char* pa_lo = cs + TILE_A;
        char* pb_hi = cs + 2 * TILE_A;
        char* pb_lo = cs + 2 * TILE_A + TILE_B;

        #pragma unroll
        for (int ks = 0; ks < 4; ks++) {
            uint32_t ahi[2][4], alo[2][4], bhi[NI][4], blo[NI][4];
            #pragma unroll
            for (int mi = 0; mi < 2; mi++) {
                int arow = wm * 32 + mi * 16 + (lane & 15);
                int ac   = ks * 2 + (lane >> 4);
                ldm_x4(ahi[mi], smem_u32(pa_hi + swz128(arow, ac)));
                ldm_x4(alo[mi], smem_u32(pa_lo + swz128(arow, ac)));
            }
            #pragma unroll
            for (int np = 0; np < NI; np++) {
                int brow = wn * (BN / 4) + np * 16 + ((lane & 16) ? 8 : 0) + (lane & 7);
                int bc   = ks * 2 + ((lane >> 3) & 1);
                ldm_x4(bhi[np], smem_u32(pb_hi + swz128(brow, bc)));
                ldm_x4(blo[np], smem_u32(pb_lo + swz128(brow, bc)));
            }
            #pragma unroll
            for (int mi = 0; mi < 2; mi++)
                #pragma unroll
                for (int np = 0; np < NI; np++)
                    #pragma unroll
                    for (int h = 0; h < 2; h++) {
                        float* a_ = acc[mi][np * 2 + h];
                        mma_bf16(a_, ahi[mi], &bhi[np][h * 2]);
                        mma_bf16(a_, alo[mi], &bhi[np][h * 2]);
                        mma_bf16(a_, ahi[mi], &blo[np][h * 2]);
                    }
        }
    }

    // epilogue
    int r0 = cm + wm * 32 + (lane >> 2);
    int c0 = cn + wn * (BN / 4) + (lane & 3) * 2;
    #pragma unroll
    for (int mi = 0; mi < 2; mi++) {
        #pragma unroll
        for (int ni = 0; ni < 2 * NI; ni++) {
            #pragma unroll
            for (int h8 = 0; h8 < 2; h8++) {
                int row = r0 + mi * 16 + h8 * 8;
                int col = c0 + ni * 8;
                float v0 = acc[mi][ni][h8 * 2 + 0];
                float v1 = acc[mi][ni][h8 * 2 + 1];
                if (g.addend) {
                    float2 ad = __ldcg((const float2*)&g.addend[(size_t)row * UNITS + col]);
                    v0 += ad.x; v1 += ad.y;
                }
                if (g.bias) {
                    float2 bi = *(const float2*)&g.bias[col];
                    v0 += bi.x; v1 += bi.y;
                }
                if (g.act) { v0 = tanhf(v0); v1 = tanhf(v1); }
                if (g.out32)
                    *(float2*)&g.out32[(size_t)row * UNITS + col] = make_float2(v0, v1);
                if (g.outE) {
                    __nv_bfloat16 h0 = __float2bfloat16(v0);
                    __nv_bfloat16 h1 = __float2bfloat16(v1);
                    __nv_bfloat16 l0 = __float2bfloat16(v0 - __bfloat162float(h0));
                    __nv_bfloat16 l1 = __float2bfloat16(v1 - __bfloat162float(h1));
                    __nv_bfloat162 hp; hp.x = h0; hp.y = h1;
                    __nv_bfloat162 lp; lp.x = l0; lp.y = l1;
                    *(__nv_bfloat162*)&g.outE[(size_t)row * g.ldo + col]         = hp;
                    *(__nv_bfloat162*)&g.outE[(size_t)row * g.ldo + UNITS + col] = lp;
                }
            }
        }
    }
}

// ---------------- standalone GEMM kernel (xw0 precompute) ---------------------
__global__ void __launch_bounds__(256)
xw0_gemm(Args g)
{
    extern __shared__ __align__(16) char sm[];
    gemm_tile<128>(g, blockIdx.y * 64, blockIdx.x * 128, sm);
}

// ---------------- persistent RNN time loop ------------------------------------
__global__ void __launch_bounds__(256)
rnn_persistent(const __nv_bfloat16* __restrict__ U0t,
               const __nv_bfloat16* __restrict__ W1t,
               const __nv_bfloat16* __restrict__ U1t,
               const float* __restrict__ xw0,
               const float* __restrict__ b1,
               float* __restrict__ pbuf,
               __nv_bfloat16* __restrict__ hbuf,
               float* __restrict__ h1f,
               unsigned* __restrict__ bar)
{
    extern __shared__ __align__(16) char sm[];
    int cid = blockIdx.x;

    __nv_bfloat16* cur = hbuf;
    __nv_bfloat16* nxt = hbuf + (size_t)BATCH * HROW;

    for (int t = 0; t < SEQ; t++) {
        // phase A: 64 CTAs -> h0' = tanh(xw0_t + h0@U0); 64 CTAs -> p = h1@U1
        {
            int unit = cid >> 6;
            int id   = cid & 63;
            int cm = (id >> 4) * 64;     // 0..3 -> 4 m-tiles
            int cn = (id & 15) * 128;    // 0..15 -> 16 n-tiles

            Args g{};
            g.nchunk = UNITS / 64; g.lda = HROW; g.ldb = WK;
            if (unit == 0) {
                g.Ahi = cur;  g.Alo = cur + 2048;
                g.Bhi = U0t;  g.Blo = U0t + 2048;
                g.addend = xw0 + (size_t)t * BATCH * UNITS; g.bias = nullptr;
                g.outE = nxt; g.ldo = HROW; g.out32 = nullptr; g.act = 1;
            } else {
                g.Ahi = cur + 4096; g.Alo = cur + 6144;
                g.Bhi = U1t;        g.Blo = U1t + 2048;
                g.addend = nullptr; g.bias = nullptr;
                g.outE = nullptr; g.ldo = 0; g.out32 = pbuf; g.act = 0;
            }
            gemm_tile<128>(g, cm, cn, sm);
        }
        grid_sync(bar, 2 * t);

        // phase B: 128 CTAs -> h1' = tanh(h0'@W1 + p + b1)
        {
            int cm = (cid >> 5) * 64;    // 0..3
            int cn = (cid & 31) * 64;    // 0..31

            Args g{};
            g.Ahi = nxt; g.Alo = nxt + 2048;
            g.Bhi = W1t; g.Blo = W1t + 2048;
            g.nchunk = UNITS / 64; g.lda = HROW; g.ldb = WK;
            g.addend = pbuf; g.bias = b1;
            g.outE = nxt + 4096; g.ldo = HROW;
            g.out32 = (t == SEQ - 1) ? h1f : nullptr; g.act = 1;
            gemm_tile<64>(g, cm, cn, sm);
        }
        grid_sync(bar, 2 * t + 1);

        __nv_bfloat16* tmp = cur; cur = nxt; nxt = tmp;
    }
}

// ---------------- prep kernels ------------------------------------------------
__global__ void wsplit_kernel(const float* __restrict__ W, __nv_bfloat16* __restrict__ out) {
    __shared__ float tile[32][33];
    int k0 = blockIdx.y * 32, n0 = blockIdx.x * 32;
    #pragma unroll
    for (int r = 0; r < 4; r++)
        tile[threadIdx.y + 8 * r][threadIdx.x] =
            W[(size_t)(k0 + threadIdx.y + 8 * r) * UNITS + n0 + threadIdx.x];
    __syncthreads();
    #pragma unroll
    for (int r = 0; r < 4; r++) {
        int n = n0 + threadIdx.y + 8 * r;
        int k = k0 + threadIdx.x;
        float w = tile[threadIdx.x][threadIdx.y + 8 * r];
        __nv_bfloat16 hi = __float2bfloat16(w);
        __nv_bfloat16 lo = __float2bfloat16(w - __bfloat162float(hi));
        out[(size_t)n * WK + k]         = hi;
        out[(size_t)n * WK + UNITS + k] = lo;
    }
}

__global__ void w0split_kernel(const float* __restrict__ W0, __nv_bfloat16* __restrict__ out) {
    int n = blockIdx.x;
    int k = threadIdx.x;
    float v = (k < EMBED) ? W0[(size_t)k * UNITS + n] : 0.f;
    __nv_bfloat16 hi = __float2bfloat16(v);
    __nv_bfloat16 lo = __float2bfloat16(v - __bfloat162float(hi));
    out[(size_t)n * XK + k]       = hi;
    out[(size_t)n * XK + 128 + k] = lo;
}

__global__ void gather_split_kernel(const int* __restrict__ inputs,
                                    const float* __restrict__ emb,
                                    __nv_bfloat16* __restrict__ xe) {
    int row = blockIdx.x;
    int t = row / BATCH, b = row % BATCH;
    int tok = inputs[b * SEQ + t];
    int k = threadIdx.x;
    float v = (k < EMBED) ? emb[(size_t)tok * EMBED + k] : 0.f;
    __nv_bfloat16 hi = __float2bfloat16(v);
    __nv_bfloat16 lo = __float2bfloat16(v - __bfloat162float(hi));
    xe[(size_t)row * XK + k]       = hi;
    xe[(size_t)row * XK + 128 + k] = lo;
}

__global__ void zero_u32_kernel(uint32_t* p, int n) {
    int i = blockIdx.x * blockDim.x + threadIdx.x;
    if (i < n) p[i] = 0u;
}

__global__ void final_kernel(const float* __restrict__ h1,
                             const float* __restrict__ Wo,
                             const float* __restrict__ bo,
                             float* __restrict__ out) {
    int b = blockIdx.x;
    float s = 0.f;
    for (int i = threadIdx.x; i < UNITS; i += blockDim.x)
        s += h1[b * UNITS + i] * Wo[i];
    for (int off = 16; off; off >>= 1) s += __shfl_down_sync(0xffffffffu, s, off);
    __shared__ float red[8];
    if ((threadIdx.x & 31) == 0) red[threadIdx.x >> 5] = s;
    __syncthreads();
    if (threadIdx.x == 0) {
        float t = 0.f;
        for (int w = 0; w < (int)(blockDim.x >> 5); w++) t += red[w];
        out[b] = 1.f / (1.f + expf(-(t + bo[0])));
    }
}

// ---------------- launch ------------------------------------------------------
extern "C" void kernel_launch(void* const* d_in, const int* in_sizes, int n_in,
                              void* d_out, int out_size)
{
    const int*   inputs = (const int*)  d_in[0];
    const float* emb    = (const float*)d_in[1];
    const float* W0     = (const float*)d_in[2];
    const float* U0     = (const float*)d_in[3];
    const float* b0     = (const float*)d_in[4];
    const float* W1     = (const float*)d_in[5];
    const float* U1     = (const float*)d_in[6];
    const float* b1     = (const float*)d_in[7];
    const float* Wo     = (const float*)d_in[8];
    const float* bo     = (const float*)d_in[9];
    float* out = (float*)d_out;

    __nv_bfloat16 *xe, *w0t, *U0t, *W1t, *U1t, *hbuf;
    float *xw0, *pbuf, *h1f;
    unsigned* bar;
    cudaGetSymbolAddress((void**)&xe,   g_xe);
    cudaGetSymbolAddress((void**)&w0t,  g_w0t);
    cudaGetSymbolAddress((void**)&U0t,  g_U0t);
    cudaGetSymbolAddress((void**)&W1t,  g_W1t);
    cudaGetSymbolAddress((void**)&U1t,  g_U1t);
    cudaGetSymbolAddress((void**)&xw0,  g_xw0);
    cudaGetSymbolAddress((void**)&pbuf, g_p);
    cudaGetSymbolAddress((void**)&hbuf, g_hbuf);
    cudaGetSymbolAddress((void**)&h1f,  g_h1f);
    cudaGetSymbolAddress((void**)&bar,  g_bar);

    const int SMEM128 = 3 * (2 * 64 * 128 + 2 * 128 * 128);   // 147456
    cudaFuncSetAttribute(xw0_gemm,
                         cudaFuncAttributeMaxDynamicSharedMemorySize, SMEM128);
    cudaFuncSetAttribute(rnn_persistent,
                         cudaFuncAttributeMaxDynamicSharedMemorySize, SMEM128);

    // weight prep
    dim3 wgrid(UNITS / 32, UNITS / 32), wblk(32, 8);
    wsplit_kernel<<<wgrid, wblk>>>(U0, U0t);
    wsplit_kernel<<<wgrid, wblk>>>(W1, W1t);
    wsplit_kernel<<<wgrid, wblk>>>(U1, U1t);
    w0split_kernel<<<UNITS, 128>>>(W0, w0t);

    // zero h state + barrier counters
    int zn = BATCH * HROW * 2 / 4;
    zero_u32_kernel<<<(zn + 255) / 256, 256>>>((uint32_t*)hbuf, zn);
    zero_u32_kernel<<<1, 256>>>((uint32_t*)bar, 2 * SEQ + 8);

    // xw0 = x @ W0 + b0
    gather_split_kernel<<<SEQ * BATCH, 128>>>(inputs, emb, xe);
    {
        Args g{};
        g.Ahi = xe; g.Alo = xe + 128; g.Bhi = w0t; g.Blo = w0t + 128;
        g.nchunk = 2; g.lda = XK; g.ldb = XK;
        g.addend = nullptr; g.bias = b0;
        g.outE = nullptr; g.ldo = 0; g.out32 = xw0; g.act = 0;
        xw0_gemm<<<dim3(UNITS / 128, (SEQ * BATCH) / 64), 256, SMEM128>>>(g);
    }

    // persistent time loop: 128 CTAs, 1 per SM, 2 grid barriers per step
    rnn_persistent<<<NCTA, 256, SMEM128>>>(U0t, W1t, U1t, xw0, b1,
                                           pbuf, hbuf, h1f, bar);

    final_kernel<<<BATCH, 256>>>(h1f, Wo, bo, out);
}

// round 8
// speedup vs baseline: 6.2186x; 1.0199x over previous
#include <cuda_runtime.h>
#include <cuda_bf16.h>
#include <math.h>
#include <stdint.h>

#define SEQ    80
#define BATCH  256
#define EMBED  100
#define UNITS  2048
#define WK     4096          // weight row: [hi(2048) | lo(2048)]
#define XK     256           // x row: [hi(128 pad) | lo(128 pad)]
#define HROW   8192          // h row: [h0hi|h0lo|h1hi|h1lo]
#define NCTA   128

// ---------------- scratch ----------------------------------------------------
__device__ __nv_bfloat16 g_xe [SEQ * BATCH * XK];
__device__ __nv_bfloat16 g_w0t[UNITS * XK];
__device__ __nv_bfloat16 g_U0t[UNITS * WK];
__device__ __nv_bfloat16 g_W1t[UNITS * WK];
__device__ __nv_bfloat16 g_U1t[UNITS * WK];
__device__ float g_xw0[SEQ * BATCH * UNITS];
__device__ float g_p  [BATCH * UNITS];             // p = h1 @ U1 (fp32)
__device__ __nv_bfloat16 g_hbuf[2][BATCH * HROW];
__device__ float g_h1f[BATCH * UNITS];
__device__ unsigned g_bar[2 * SEQ + 8];            // grid-barrier counters

// ---------------- PTX helpers -------------------------------------------------
__device__ __forceinline__ uint32_t smem_u32(const void* p) {
    uint32_t a;
    asm("{ .reg .u64 t; cvta.to.shared.u64 t, %1; cvt.u32.u64 %0, t; }" : "=r"(a) : "l"(p));
    return a;
}
#define CP_ASYNC16(sp, gp) \
    asm volatile("cp.async.cg.shared.global [%0], [%1], 16;" :: "r"(sp), "l"(gp))
#define CP_COMMIT()  asm volatile("cp.async.commit_group;")
#define CP_WAIT2()   asm volatile("cp.async.wait_group 2;")
#define CP_WAIT0()   asm volatile("cp.async.wait_group 0;")

__device__ __forceinline__ void ldm_x4(uint32_t* r, uint32_t addr) {
    asm volatile("ldmatrix.sync.aligned.m8n8.x4.shared.b16 {%0,%1,%2,%3}, [%4];"
                 : "=r"(r[0]), "=r"(r[1]), "=r"(r[2]), "=r"(r[3]) : "r"(addr));
}
__device__ __forceinline__ void mma_bf16(float* d, const uint32_t* a, const uint32_t* b) {
    asm volatile("mma.sync.aligned.m16n8k16.row.col.f32.bf16.bf16.f32 "
                 "{%0,%1,%2,%3}, {%4,%5,%6,%7}, {%8,%9}, {%0,%1,%2,%3};"
                 : "+f"(d[0]), "+f"(d[1]), "+f"(d[2]), "+f"(d[3])
                 : "r"(a[0]), "r"(a[1]), "r"(a[2]), "r"(a[3]), "r"(b[0]), "r"(b[1]));
}

__device__ __forceinline__ int swz128(int row, int c16) {
    return row * 128 + ((c16 ^ (row & 7)) << 4);
}

// grid-wide barrier: one counter slot per use, all NCTA CTAs must arrive.
__device__ __forceinline__ void grid_sync(unsigned* bar, int s) {
    __syncthreads();
    if (threadIdx.x == 0) {
        __threadfence();
        atomicAdd(&bar[s], 1u);
        while (*((volatile unsigned*)&bar[s]) < NCTA) __nanosleep(32);
    }
    __syncthreads();
}

// ---------------- split-GEMM tile (3-term hi/lo) ------------------------------
struct Args {
    const __nv_bfloat16 *Ahi, *Alo, *Bhi, *Blo;
    int  nchunk;                  // K / 64
    long lda, ldb;
    const float* addend;          // [M,2048] or null (read via __ldcg)
    const float* bias;            // [2048] or null
    __nv_bfloat16* outE;          // hi @ col n, lo @ col n+2048; or null
    long ldo;
    float* out32;                 // [M,2048] or null
    int  act;
};

template<int NROWS>
__device__ __forceinline__ void load_rows(const __nv_bfloat16* src, long ld,
                                          int rbase, int kc, char* dst, int tid) {
    #pragma unroll
    for (int i = 0; i < NROWS * 8 / 256; i++) {
        int s = tid + i * 256;
        int row = s >> 3, c16 = s & 7;
        const void* g = src + (size_t)(rbase + row) * ld + kc * 64 + c16 * 8;
        CP_ASYNC16(smem_u32(dst + swz128(row, c16)), g);
    }
}

// BM=64, BK=64. 256 threads, 8 warps (2m x 4n); warp tile 32 x (BN/4).
// 4-stage cp.async ring, wait_group 2 keeps 2 chunks in flight.
template<int BN>
__device__ void gemm_tile(const Args& g, int cm, int cn, char* sm)
{
    constexpr int NI = BN / 64;
    constexpr int TILE_A = 64 * 128;
    constexpr int TILE_B = BN * 128;
    constexpr int STAGE  = 2 * TILE_A + 2 * TILE_B;

    int tid  = threadIdx.x;
    int lane = tid & 31;
    int wid  = tid >> 5;
    int wm   = wid >> 2;
    int wn   = wid & 3;

    float acc[2][2 * NI][4];
    #pragma unroll
    for (int i = 0; i < 2; i++)
        #pragma unroll
        for (int j = 0; j < 2 * NI; j++)
            #pragma unroll
            for (int k = 0; k < 4; k++) acc[i][j][k] = 0.f;

    int NC = g.nchunk;

    auto issue = [&](int c) {
        char* st = sm + (c & 3) * STAGE;
        load_rows<64>(g.Ahi, g.lda, cm, c, st,              tid);
        load_rows<64>(g.Alo, g.lda, cm, c, st + TILE_A,     tid);
        load_rows<BN>(g.Bhi, g.ldb, cn, c, st + 2 * TILE_A, tid);
        load_rows<BN>(g.Blo, g.ldb, cn, c, st + 2 * TILE_A + TILE_B, tid);
        CP_COMMIT();
    };

    issue(0);
    if (NC > 1) issue(1);
    if (NC > 2) issue(2);

    for (int c = 0; c < NC; c++) {
        if (c + 2 < NC) { CP_WAIT2(); } else { CP_WAIT0(); }
        __syncthreads();
        if (c + 3 < NC) issue(c + 3);

        char* cs = sm + (c & 3) * STAGE;
        char* pa_hi = cs;
        char* pa_lo = cs + TILE_A;
        char* pb_hi = cs + 2 * TILE_A;
        char* pb_lo = cs + 2 * TILE_A + TILE_B;

        #pragma unroll
        for (int ks = 0; ks < 4; ks++) {
            uint32_t ahi[2][4], alo[2][4], bhi[NI][4], blo[NI][4];
            #pragma unroll
            for (int mi = 0; mi < 2; mi++) {
                int arow = wm * 32 + mi * 16 + (lane & 15);
                int ac   = ks * 2 + (lane >> 4);
                ldm_x4(ahi[mi], smem_u32(pa_hi + swz128(arow, ac)));
                ldm_x4(alo[mi], smem_u32(pa_lo + swz128(arow, ac)));
            }
            #pragma unroll
            for (int np = 0; np < NI; np++) {
                int brow = wn * (BN / 4) + np * 16 + ((lane & 16) ? 8 : 0) + (lane & 7);
                int bc   = ks * 2 + ((lane >> 3) & 1);
                ldm_x4(bhi[np], smem_u32(pb_hi + swz128(brow, bc)));
                ldm_x4(blo[np], smem_u32(pb_lo + swz128(brow, bc)));
            }
            #pragma unroll
            for (int mi = 0; mi < 2; mi++)
                #pragma unroll
                for (int np = 0; np < NI; np++)
                    #pragma unroll
                    for (int h = 0; h < 2; h++) {
                        float* a_ = acc[mi][np * 2 + h];
                        mma_bf16(a_, ahi[mi], &bhi[np][h * 2]);
                        mma_bf16(a_, alo[mi], &bhi[np][h * 2]);
                        mma_bf16(a_, ahi[mi], &blo[np][h * 2]);
                    }
        }
        // buffer (c&3) reused by issue(c+4); the sync at iter c+1 precedes it.
    }

    // epilogue
    int r0 = cm + wm * 32 + (lane >> 2);
    int c0 = cn + wn * (BN / 4) + (lane & 3) * 2;
    #pragma unroll
    for (int mi = 0; mi < 2; mi++) {
        #pragma unroll
        for (int ni = 0; ni < 2 * NI; ni++) {
            #pragma unroll
            for (int h8 = 0; h8 < 2; h8++) {
                int row = r0 + mi * 16 + h8 * 8;
                int col = c0 + ni * 8;
                float v0 = acc[mi][ni][h8 * 2 + 0];
                float v1 = acc[mi][ni][h8 * 2 + 1];
                if (g.addend) {
                    float2 ad = __ldcg((const float2*)&g.addend[(size_t)row * UNITS + col]);
                    v0 += ad.x; v1 += ad.y;
                }
                if (g.bias) {
                    float2 bi = *(const float2*)&g.bias[col];
                    v0 += bi.x; v1 += bi.y;
                }
                if (g.act) { v0 = tanhf(v0); v1 = tanhf(v1); }
                if (g.out32)
                    *(float2*)&g.out32[(size_t)row * UNITS + col] = make_float2(v0, v1);
                if (g.outE) {
                    __nv_bfloat16 h0 = __float2bfloat16(v0);
                    __nv_bfloat16 h1 = __float2bfloat16(v1);
                    __nv_bfloat16 l0 = __float2bfloat16(v0 - __bfloat162float(h0));
                    __nv_bfloat16 l1 = __float2bfloat16(v1 - __bfloat162float(h1));
                    __nv_bfloat162 hp; hp.x = h0; hp.y = h1;
                    __nv_bfloat162 lp; lp.x = l0; lp.y = l1;
                    *(__nv_bfloat162*)&g.outE[(size_t)row * g.ldo + col]         = hp;
                    *(__nv_bfloat162*)&g.outE[(size_t)row * g.ldo + UNITS + col] = lp;
                }
            }
        }
    }
}

// ---------------- standalone GEMM kernel (xw0 precompute) ---------------------
__global__ void __launch_bounds__(256)
xw0_gemm(Args g)
{
    extern __shared__ __align__(16) char sm[];
    gemm_tile<128>(g, blockIdx.y * 64, blockIdx.x * 128, sm);
}

// ---------------- persistent RNN time loop ------------------------------------
__global__ void __launch_bounds__(256)
rnn_persistent(const __nv_bfloat16* __restrict__ U0t,
               const __nv_bfloat16* __restrict__ W1t,
               const __nv_bfloat16* __restrict__ U1t,
               const float* __restrict__ xw0,
               const float* __restrict__ b1,
               float* __restrict__ pbuf,
               __nv_bfloat16* __restrict__ hbuf,
               float* __restrict__ h1f,
               unsigned* __restrict__ bar)
{
    extern __shared__ __align__(16) char sm[];
    int cid = blockIdx.x;

    __nv_bfloat16* cur = hbuf;
    __nv_bfloat16* nxt = hbuf + (size_t)BATCH * HROW;

    for (int t = 0; t < SEQ; t++) {
        // phase A: 64 CTAs -> h0' = tanh(xw0_t + h0@U0); 64 CTAs -> p = h1@U1
        {
            int unit = cid >> 6;
            int id   = cid & 63;
            int cm = (id >> 4) * 64;     // 0..3 -> 4 m-tiles
            int cn = (id & 15) * 128;    // 0..15 -> 16 n-tiles

            Args g{};
            g.nchunk = UNITS / 64; g.lda = HROW; g.ldb = WK;
            if (unit == 0) {
                g.Ahi = cur;  g.Alo = cur + 2048;
                g.Bhi = U0t;  g.Blo = U0t + 2048;
                g.addend = xw0 + (size_t)t * BATCH * UNITS; g.bias = nullptr;
                g.outE = nxt; g.ldo = HROW; g.out32 = nullptr; g.act = 1;
            } else {
                g.Ahi = cur + 4096; g.Alo = cur + 6144;
                g.Bhi = U1t;        g.Blo = U1t + 2048;
                g.addend = nullptr; g.bias = nullptr;
                g.outE = nullptr; g.ldo = 0; g.out32 = pbuf; g.act = 0;
            }
            gemm_tile<128>(g, cm, cn, sm);
        }
        grid_sync(bar, 2 * t);

        // phase B: 128 CTAs -> h1' = tanh(h0'@W1 + p + b1)
        {
            int cm = (cid >> 5) * 64;    // 0..3
            int cn = (cid & 31) * 64;    // 0..31

            Args g{};
            g.Ahi = nxt; g.Alo = nxt + 2048;
            g.Bhi = W1t; g.Blo = W1t + 2048;
            g.nchunk = UNITS / 64; g.lda = HROW; g.ldb = WK;
            g.addend = pbuf; g.bias = b1;
            g.outE = nxt + 4096; g.ldo = HROW;
            g.out32 = (t == SEQ - 1) ? h1f : nullptr; g.act = 1;
            gemm_tile<64>(g, cm, cn, sm);
        }
        grid_sync(bar, 2 * t + 1);

        __nv_bfloat16* tmp = cur; cur = nxt; nxt = tmp;
    }
}

// ---------------- consolidated prep kernel -------------------------------------
// grid (64,64,6), block (32,8).
//  z=0..2 : transpose+split U0/W1/U1 -> U0t/W1t/U1t
//  z=3    : split W0 -> w0t
//  z=4    : embedding gather + split -> xe
//  z=5    : zero h-state buffer 0
__global__ void prep_all(const float* __restrict__ U0, const float* __restrict__ W1,
                         const float* __restrict__ U1, const float* __restrict__ W0,
                         const int* __restrict__ inputs, const float* __restrict__ emb,
                         __nv_bfloat16* __restrict__ U0t, __nv_bfloat16* __restrict__ W1t,
                         __nv_bfloat16* __restrict__ U1t, __nv_bfloat16* __restrict__ w0t,
                         __nv_bfloat16* __restrict__ xe,  uint32_t* __restrict__ hzero)
{
    __shared__ float tile[32][33];
    int z = blockIdx.z;
    if (z < 3) {
        const float* W = (z == 0) ? U0 : (z == 1) ? W1 : U1;
        __nv_bfloat16* out = (z == 0) ? U0t : (z == 1) ? W1t : U1t;
        int k0 = blockIdx.y * 32, n0 = blockIdx.x * 32;
        #pragma unroll
        for (int r = 0; r < 4; r++)
            tile[threadIdx.y + 8 * r][threadIdx.x] =
                W[(size_t)(k0 + threadIdx.y + 8 * r) * UNITS + n0 + threadIdx.x];
        __syncthreads();
        #pragma unroll
        for (int r = 0; r < 4; r++) {
            int n = n0 + threadIdx.y + 8 * r;
            int k = k0 + threadIdx.x;
            float w = tile[threadIdx.x][threadIdx.y + 8 * r];
            __nv_bfloat16 hi = __float2bfloat16(w);
            __nv_bfloat16 lo = __float2bfloat16(w - __bfloat162float(hi));
            out[(size_t)n * WK + k]         = hi;
            out[(size_t)n * WK + UNITS + k] = lo;
        }
        return;
    }
    int tid = threadIdx.y * 32 + threadIdx.x;          // 0..255
    int bid = blockIdx.y * 64 + blockIdx.x;            // 0..4095
    int gid = bid * 256 + tid;                         // 0..1048575
    if (z == 3) {
        if (gid < UNITS * 128) {
            int n = gid >> 7, k = gid & 127;
            float v = (k < EMBED) ? W0[(size_t)k * UNITS + n] : 0.f;
            __nv_bfloat16 hi = __float2bfloat16(v);
            __nv_bfloat16 lo = __float2bfloat16(v - __bfloat162float(hi));
            w0t[(size_t)n * XK + k]       = hi;
            w0t[(size_t)n * XK + 128 + k] = lo;
        }
    } else if (z == 4) {
        for (int w = gid; w < SEQ * BATCH * 128; w += 4096 * 256) {
            int row = w >> 7, k = w & 127;
            int t = row / BATCH, b = row % BATCH;
            int tok = inputs[b * SEQ + t];
            float v = (k < EMBED) ? emb[(size_t)tok * EMBED + k] : 0.f;
            __nv_bfloat16 hi = __float2bfloat16(v);
            __nv_bfloat16 lo = __float2bfloat16(v - __bfloat162float(hi));
            xe[(size_t)row * XK + k]       = hi;
            xe[(size_t)row * XK + 128 + k] = lo;
        }
    } else {
        // zero h buffer 0: BATCH*HROW bf16 = 1,048,576 u32 slots
        hzero[gid] = 0u;
    }
}

__global__ void zero_bar_kernel(unsigned* bar) {
    if (threadIdx.x < 2 * SEQ + 8) bar[threadIdx.x] = 0u;
}

__global__ void final_kernel(const float* __restrict__ h1,
                             const float* __restrict__ Wo,
                             const float* __restrict__ bo,
                             float* __restrict__ out) {
    int b = blockIdx.x;
    float s = 0.f;
    for (int i = threadIdx.x; i < UNITS; i += blockDim.x)
        s += h1[b * UNITS + i] * Wo[i];
    for (int off = 16; off; off >>= 1) s += __shfl_down_sync(0xffffffffu, s, off);
    __shared__ float red[8];
    if ((threadIdx.x & 31) == 0) red[threadIdx.x >> 5] = s;
    __syncthreads();
    if (threadIdx.x == 0) {
        float t = 0.f;
        for (int w = 0; w < (int)(blockDim.x >> 5); w++) t += red[w];
        out[b] = 1.f / (1.f + expf(-(t + bo[0])));
    }
}

// ---------------- launch ------------------------------------------------------
extern "C" void kernel_launch(void* const* d_in, const int* in_sizes, int n_in,
                              void* d_out, int out_size)
{
    const int*   inputs = (const int*)  d_in[0];
    const float* emb    = (const float*)d_in[1];
    const float* W0     = (const float*)d_in[2];
    const float* U0     = (const float*)d_in[3];
    const float* b0     = (const float*)d_in[4];
    const float* W1     = (const float*)d_in[5];
    const float* U1     = (const float*)d_in[6];
    const float* b1     = (const float*)d_in[7];
    const float* Wo     = (const float*)d_in[8];
    const float* bo     = (const float*)d_in[9];
    float* out = (float*)d_out;

    __nv_bfloat16 *xe, *w0t, *U0t, *W1t, *U1t, *hbuf;
    float *xw0, *pbuf, *h1f;
    unsigned* bar;
    cudaGetSymbolAddress((void**)&xe,   g_xe);
    cudaGetSymbolAddress((void**)&w0t,  g_w0t);
    cudaGetSymbolAddress((void**)&U0t,  g_U0t);
    cudaGetSymbolAddress((void**)&W1t,  g_W1t);
    cudaGetSymbolAddress((void**)&U1t,  g_U1t);
    cudaGetSymbolAddress((void**)&xw0,  g_xw0);
    cudaGetSymbolAddress((void**)&pbuf, g_p);
    cudaGetSymbolAddress((void**)&hbuf, g_hbuf);
    cudaGetSymbolAddress((void**)&h1f,  g_h1f);
    cudaGetSymbolAddress((void**)&bar,  g_bar);

    const int SMEM128 = 4 * (2 * 64 * 128 + 2 * 128 * 128);   // 196608 (4 stages)
    cudaFuncSetAttribute(xw0_gemm,
                         cudaFuncAttributeMaxDynamicSharedMemorySize, SMEM128);
    cudaFuncSetAttribute(rnn_persistent,
                         cudaFuncAttributeMaxDynamicSharedMemorySize, SMEM128);

    // launch 0: all prep (weight splits, W0 split, gather, h zero)
    prep_all<<<dim3(64, 64, 6), dim3(32, 8)>>>(U0, W1, U1, W0, inputs, emb,
                                               U0t, W1t, U1t, w0t, xe,
                                               (uint32_t*)hbuf);

    // launch 1: xw0 = x @ W0 + b0
    {
        Args g{};
        g.Ahi = xe; g.Alo = xe + 128; g.Bhi = w0t; g.Blo = w0t + 128;
        g.nchunk = 2; g.lda = XK; g.ldb = XK;
        g.addend = nullptr; g.bias = b0;
        g.outE = nullptr; g.ldo = 0; g.out32 = xw0; g.act = 0;
        xw0_gemm<<<dim3(UNITS / 128, (SEQ * BATCH) / 64), 256, SMEM128>>>(g);
    }

    // launch 2: zero barrier counters
    zero_bar_kernel<<<1, 256>>>(bar);

    // launch 3: persistent time loop (profiled slot)
    rnn_persistent<<<NCTA, 256, SMEM128>>>(U0t, W1t, U1t, xw0, b1,
                                           pbuf, hbuf, h1f, bar);

    // launch 4: output head
    final_kernel<<<BATCH, 256>>>(h1f, Wo, bo, out);
}